// round 10
// baseline (speedup 1.0000x reference)
#include <cuda_runtime.h>
#include <cuda_bf16.h>
#include <cstdint>
#include <math.h>

#define Bn  16
#define Sn  256
#define Hn  768
#define H1n 769
#define Ln  37
#define Yn  512
#define PK  768      // K (24*32), bias column handled as rank-1 terms
#define KCH 24

typedef long long ll;
typedef unsigned int u32;
typedef __nv_bfloat16 bf16;

#define TILE_B   10240     // 128 rows x 40 bf16 (80B padded rows)
#define STAGE_B  40960
#define SMEM_DYN 81920

// ---------------- static scratch ----------------
__device__ __align__(256) bf16  g_xa_h[(size_t)Bn*128*PK];
__device__ __align__(256) bf16  g_xa_l[(size_t)Bn*128*PK];
__device__ __align__(256) float g_xaf [(size_t)Bn*128*PK];
__device__ __align__(256) bf16  g_yr_h[(size_t)Bn*Yn*PK];
__device__ __align__(256) bf16  g_yr_l[(size_t)Bn*Yn*PK];
__device__ __align__(256) float g_yrf [(size_t)Bn*Yn*PK];
__device__ __align__(256) bf16  g_Wrt_h[(size_t)Ln*PK*PK];
__device__ __align__(256) bf16  g_Wrt_l[(size_t)Ln*PK*PK];
__device__ __align__(256) bf16  g_Wat_h[(size_t)PK*PK];
__device__ __align__(256) bf16  g_Wat_l[(size_t)PK*PK];
__device__ __align__(256) float g_brel[(size_t)Ln*H1n];   // W_rel[o][768][:]
__device__ __align__(256) float g_wcol[(size_t)Ln*H1n];   // W_rel[o][:][768]
__device__ __align__(256) float g_barc[(size_t)Hn];       // W_arc[768][:]
__device__ __align__(256) bf16  g_T_h[(size_t)Bn*Ln*128*PK];
__device__ __align__(256) bf16  g_T_l[(size_t)Bn*Ln*128*PK];
__device__ __align__(256) bf16  g_U_h[(size_t)Bn*128*PK];
__device__ __align__(256) bf16  g_U_l[(size_t)Bn*128*PK];
__device__ __align__(256) float g_tcol[(size_t)Bn*Ln*128];
__device__ __align__(256) float g_R[(size_t)Bn*Ln*128*Yn];
__device__ float g_rrel[(size_t)Bn*Yn*Ln];
__device__ float g_rarc[(size_t)Bn*Yn];
__device__ float g_arc_sum, g_rel_sum;
__device__ int   g_n;

// ---------------- helpers ----------------
__device__ __forceinline__ u32 smem_u32(const void* p){
    u32 a; asm("{ .reg .u64 t; cvta.to.shared.u64 t, %1; cvt.u32.u64 %0, t; }" : "=r"(a) : "l"(p));
    return a;
}
__device__ __forceinline__ void ldsm4(u32* d, u32 addr){
    asm volatile("ldmatrix.sync.aligned.m8n8.x4.shared.b16 {%0,%1,%2,%3}, [%4];"
        : "=r"(d[0]), "=r"(d[1]), "=r"(d[2]), "=r"(d[3]) : "r"(addr));
}
__device__ __forceinline__ void mma16816(float* c, const u32* a, u32 b0, u32 b1){
    asm volatile("mma.sync.aligned.m16n8k16.row.col.f32.bf16.bf16.f32 "
        "{%0,%1,%2,%3}, {%4,%5,%6,%7}, {%8,%9}, {%0,%1,%2,%3};"
        : "+f"(c[0]), "+f"(c[1]), "+f"(c[2]), "+f"(c[3])
        : "r"(a[0]), "r"(a[1]), "r"(a[2]), "r"(a[3]), "r"(b0), "r"(b1));
}
__device__ __forceinline__ void cpasync16(u32 dst, const void* src){
    asm volatile("cp.async.cg.shared.global [%0], [%1], 16;" :: "r"(dst), "l"(src) : "memory");
}
#define CP_COMMIT() asm volatile("cp.async.commit_group;" ::: "memory")
#define CP_WAIT0()  asm volatile("cp.async.wait_group 0;" ::: "memory")

__device__ __forceinline__ void split2(float f0, float f1, u32& hp, u32& lp){
    u32 h;
    asm("cvt.rn.bf16x2.f32 %0, %1, %2;" : "=r"(h) : "f"(f1), "f"(f0));
    float h0 = __uint_as_float(h << 16);
    float h1 = __uint_as_float(h & 0xffff0000u);
    asm("cvt.rn.bf16x2.f32 %0, %1, %2;" : "=r"(lp) : "f"(f1 - h1), "f"(f0 - h0));
    hp = h;
}

// ---------------- weight repack: transpose + split (768x768 exact) ----------------
__global__ void repack_wrel(const float* __restrict__ W, bf16* __restrict__ Wh, bf16* __restrict__ Wl){
    __shared__ float sm[32][33];
    int o = blockIdx.z, i0 = blockIdx.x*32, j0 = blockIdx.y*32;
    int tx = threadIdx.x & 31, ty = threadIdx.x >> 5;
    for (int r = ty; r < 32; r += 8)
        sm[r][tx] = W[((size_t)o*H1n + i0 + r)*H1n + j0 + tx];
    __syncthreads();
    for (int r = ty; r < 32; r += 8){
        int j = j0 + r, i = i0 + tx;
        float v = sm[tx][r];
        bf16 h = __float2bfloat16_rn(v);
        size_t d = ((size_t)o*PK + j)*PK + i;
        Wh[d] = h; Wl[d] = __float2bfloat16_rn(v - __bfloat162float(h));
    }
}
__global__ void repack_warc(const float* __restrict__ W, bf16* __restrict__ Wh, bf16* __restrict__ Wl){
    __shared__ float sm[32][33];
    int i0 = blockIdx.x*32, j0 = blockIdx.y*32;
    int tx = threadIdx.x & 31, ty = threadIdx.x >> 5;
    for (int r = ty; r < 32; r += 8)
        sm[r][tx] = W[(size_t)(i0 + r)*Hn + j0 + tx];
    __syncthreads();
    for (int r = ty; r < 32; r += 8){
        int j = j0 + r, i = i0 + tx;
        float v = sm[tx][r];
        bf16 h = __float2bfloat16_rn(v);
        size_t d = (size_t)j*PK + i;
        Wh[d] = h; Wl[d] = __float2bfloat16_rn(v - __bfloat162float(h));
    }
}

// extract bias rows/cols
__global__ void extract_bias(const float* __restrict__ Wrel, const float* __restrict__ Warc,
                             float* __restrict__ brel, float* __restrict__ wcol, float* __restrict__ barc){
    int o = blockIdx.x, t = threadIdx.x;
    if (o < Ln){
        for (int j = t; j < H1n; j += 256){
            brel[(size_t)o*H1n + j] = Wrel[((size_t)o*H1n + Hn)*H1n + j];
            wcol[(size_t)o*H1n + j] = Wrel[((size_t)o*H1n + j)*H1n + Hn];
        }
    } else {
        for (int j = t; j < Hn; j += 256) barc[j] = Warc[(size_t)Hn*Hn + j];
    }
}

// ---------------- build xa/yr (segment mean, split, K=768) ----------------
__global__ void build_kernel(const float* __restrict__ hidden, const int* __restrict__ ws,
                             bf16* __restrict__ xah, bf16* __restrict__ xal, float* __restrict__ xaf,
                             bf16* __restrict__ yrh, bf16* __restrict__ yrl, float* __restrict__ yrf){
    int j = blockIdx.x, b = blockIdx.y, t = threadIdx.x;
    __shared__ int sws[Sn];
    int myws = ws[b*Sn + t];
    sws[t] = myws;
    int n_valid = __syncthreads_count(myws != 0);
    int start = sws[j];
    int end = (j+1 < Sn) ? sws[j+1] : 0;
    bool valid = (j+1) < n_valid;
    int len = end - start; if (len < 1) len = 1;
    float inv = 1.0f/(float)len;
    const float* hb = hidden + (size_t)b*Sn*Hn;
    size_t yj = ((size_t)b*Yn + j)*PK;
    size_t yd = ((size_t)b*Yn + Sn + j)*PK;
    size_t xj = ((size_t)b*128 + j)*PK;
    for (int h = t; h < PK; h += 256){
        float hv = hb[(size_t)j*Hn + h];
        float dv = 0.f;
        if (valid){
            float s = 0.f;
            for (int tok = start; tok < end; ++tok) s += hb[(size_t)tok*Hn + h];
            dv = s*inv;
        }
        bf16 hh = __float2bfloat16_rn(hv);
        bf16 dh = __float2bfloat16_rn(dv);
        yrh[yj+h] = hh; yrl[yj+h] = __float2bfloat16_rn(hv - __bfloat162float(hh));
        yrf[yj+h] = hv;
        yrh[yd+h] = dh; yrl[yd+h] = __float2bfloat16_rn(dv - __bfloat162float(dh));
        yrf[yd+h] = dv;
        if (j < 128){
            xah[xj+h] = dh; xal[xj+h] = __float2bfloat16_rn(dv - __bfloat162float(dh));
            xaf[xj+h] = dv;
        }
    }
}

__global__ void prep_kernel(const int* __restrict__ la){
    int t = threadIdx.x, cnt = 0;
    for (int i = t; i < Bn*Sn; i += 256) cnt += (la[i] != 0);
    __shared__ int sc[256];
    sc[t] = cnt; __syncthreads();
    for (int s2 = 128; s2 > 0; s2 >>= 1){ if (t < s2) sc[t] += sc[t+s2]; __syncthreads(); }
    if (t == 0){ g_n = sc[0]; g_arc_sum = 0.f; g_rel_sum = 0.f; }
}

// tcol[b][o][x] = dot(xaf[b][x], wcol[o][0..767]) + wcol[o][768]
__global__ void tcol_kernel(const float* __restrict__ xaf, const float* __restrict__ wcol,
                            float* __restrict__ tcol){
    int o = blockIdx.x, b = blockIdx.y;
    int t = threadIdx.x;
    __shared__ float sw[PK];
    for (int i = t; i < PK; i += 128) sw[i] = wcol[(size_t)o*H1n + i];
    __syncthreads();
    const float* xr = xaf + ((size_t)b*128 + t)*PK;
    float s = wcol[(size_t)o*H1n + Hn];
    #pragma unroll 4
    for (int i = 0; i < PK; i += 4){
        float4 xv = *(const float4*)(xr + i);
        s += xv.x*sw[i] + xv.y*sw[i+1] + xv.z*sw[i+2] + xv.w*sw[i+3];
    }
    tcol[((size_t)b*Ln + o)*128 + t] = s;
}

// ---------------- HMMA GEMM, cp.async 2-stage, frag-reuse 3-pass, 2 CTAs/SM ----------------
// EPI 0: +bias row (fp32), split -> Ch/Cl bf16.
// EPI 1: +rowadd[rr], fp32 float2 stores.
// EPI 2: fp32 scalar stores (4B-aligned dest), no adds.
template<int EPI>
__global__ void __launch_bounds__(256, 2)
mma_gemm(const bf16* __restrict__ Ah, const bf16* __restrict__ Al, ll lda,
         const bf16* __restrict__ Bh, const bf16* __restrict__ Bl, ll ldb,
         bf16* __restrict__ Ch, bf16* __restrict__ Cl, float* __restrict__ Cf, ll ldc,
         int P, ll pA, ll qA, ll pB, ll qB, ll pC, ll qC,
         const float* __restrict__ bias, ll pBias,
         const float* __restrict__ rowadd, ll pRow, ll qRow){
    extern __shared__ char smem[];
    const u32 sb = smem_u32(smem);

    const int tid = threadIdx.x;
    const int lane = tid & 31, wid = tid >> 5;
    const int wm = wid & 1, wn = wid >> 1;

    int z = blockIdx.z, zp = z / P, zq = z - zp*P;
    int col0 = blockIdx.x * 128;
    const bf16* A0h = Ah + (size_t)(zp*pA + zq*qA);
    const bf16* A0l = Al + (size_t)(zp*pA + zq*qA);
    const bf16* B0h = Bh + (size_t)(zp*pB + zq*qB) + (size_t)col0*ldb;
    const bf16* B0l = Bl + (size_t)(zp*pB + zq*qB) + (size_t)col0*ldb;

    const int cr0 = tid >> 2;
    const int cs  = tid & 3;
    auto issue = [&](int c){
        int k0 = c * 32;
        const bf16* s0 = A0h + k0; const bf16* s1 = A0l + k0;
        const bf16* s2 = B0h + k0; const bf16* s3 = B0l + k0;
        u32 base = sb + (u32)(c & 1) * STAGE_B;
        #pragma unroll
        for (int rep = 0; rep < 2; rep++){
            int row = cr0 + rep*64;
            u32 doff = (u32)(row*80 + cs*16);
            cpasync16(base + 0*TILE_B + doff, s0 + (size_t)row*lda + cs*8);
            cpasync16(base + 1*TILE_B + doff, s1 + (size_t)row*lda + cs*8);
            cpasync16(base + 2*TILE_B + doff, s2 + (size_t)row*ldb + cs*8);
            cpasync16(base + 3*TILE_B + doff, s3 + (size_t)row*ldb + cs*8);
        }
        CP_COMMIT();
    };

    float acc[4][4][4];
    #pragma unroll
    for (int i = 0; i < 4; i++)
        #pragma unroll
        for (int j = 0; j < 4; j++)
            #pragma unroll
            for (int k = 0; k < 4; k++) acc[i][j][k] = 0.f;

    const int arow = wm*64 + (lane & 15);
    const int aseg = (lane >> 4) * 8;
    const int bg   = lane >> 3;
    const int brow_in = (lane & 7);
    const int brow_base = wn*32 + ((bg >> 1) << 3) + brow_in;
    const int bseg = (bg & 1) * 8;

    issue(0);

    #pragma unroll 1
    for (int c = 0; c < KCH; ++c){
        CP_WAIT0();
        __syncthreads();              // single barrier per stage
        if (c + 1 < KCH) issue(c + 1);

        u32 sbase = sb + (u32)(c & 1) * STAGE_B;
        #pragma unroll
        for (int ks = 0; ks < 2; ks++){
            // fragment loads (once per ks, shared across the 3 split passes)
            u32 ah[4][4], al[4][4];
            u32 bh[2][4], blf[2][4];
            #pragma unroll
            for (int mi = 0; mi < 4; mi++)
                ldsm4(ah[mi], sbase + (u32)((arow + mi*16)*40 + ks*16 + aseg)*2u);
            #pragma unroll
            for (int nh = 0; nh < 2; nh++)
                ldsm4(bh[nh], sbase + 2u*TILE_B + (u32)((brow_base + nh*16)*40 + ks*16 + bseg)*2u);
            #pragma unroll
            for (int nh = 0; nh < 2; nh++)
                ldsm4(blf[nh], sbase + 3u*TILE_B + (u32)((brow_base + nh*16)*40 + ks*16 + bseg)*2u);
            #pragma unroll
            for (int mi = 0; mi < 4; mi++)
                ldsm4(al[mi], sbase + TILE_B + (u32)((arow + mi*16)*40 + ks*16 + aseg)*2u);

            // pass hh: Ah x Bh
            #pragma unroll
            for (int mi = 0; mi < 4; mi++)
                #pragma unroll
                for (int ni = 0; ni < 4; ni++)
                    mma16816(acc[mi][ni], ah[mi], bh[ni>>1][(ni&1)*2], bh[ni>>1][(ni&1)*2+1]);
            // pass hl: Ah x Bl
            #pragma unroll
            for (int mi = 0; mi < 4; mi++)
                #pragma unroll
                for (int ni = 0; ni < 4; ni++)
                    mma16816(acc[mi][ni], ah[mi], blf[ni>>1][(ni&1)*2], blf[ni>>1][(ni&1)*2+1]);
            // pass lh: Al x Bh
            #pragma unroll
            for (int mi = 0; mi < 4; mi++)
                #pragma unroll
                for (int ni = 0; ni < 4; ni++)
                    mma16816(acc[mi][ni], al[mi], bh[ni>>1][(ni&1)*2], bh[ni>>1][(ni&1)*2+1]);
        }
    }

    ll cofs = (ll)zp*pC + (ll)zq*qC;
    const float* bp = (EPI == 0) ? (bias + zp*pBias) : nullptr;
    const float* rp = (EPI == 1) ? (rowadd + zp*pRow + zq*qRow) : nullptr;

    #pragma unroll
    for (int mi = 0; mi < 4; mi++){
        int rr = wm*64 + mi*16 + (lane >> 2);
        #pragma unroll
        for (int ni = 0; ni < 4; ni++){
            int cc = col0 + wn*32 + ni*8 + (lane & 3)*2;
            float* cr = acc[mi][ni];
            if (EPI == 0){
                float bv0 = bp[cc], bv1 = bp[cc+1];
                u32 h0, l0, h1, l1;
                split2(cr[0]+bv0, cr[1]+bv1, h0, l0);
                split2(cr[2]+bv0, cr[3]+bv1, h1, l1);
                *(u32*)(Ch + cofs + (size_t)rr*ldc + cc)     = h0;
                *(u32*)(Cl + cofs + (size_t)rr*ldc + cc)     = l0;
                *(u32*)(Ch + cofs + (size_t)(rr+8)*ldc + cc) = h1;
                *(u32*)(Cl + cofs + (size_t)(rr+8)*ldc + cc) = l1;
            } else if (EPI == 1){
                float r0 = rp[rr], r1 = rp[rr+8];
                *(float2*)(Cf + cofs + (size_t)rr*ldc + cc)     = make_float2(cr[0]+r0, cr[1]+r0);
                *(float2*)(Cf + cofs + (size_t)(rr+8)*ldc + cc) = make_float2(cr[2]+r1, cr[3]+r1);
            } else {
                float* p0 = Cf + cofs + (size_t)rr*ldc + cc;
                float* p1 = Cf + cofs + (size_t)(rr+8)*ldc + cc;
                p0[0] = cr[0]; p0[1] = cr[1];
                p1[0] = cr[2]; p1[1] = cr[3];
            }
        }
    }
}

// ---------------- bias rows (exact fp32) ----------------
__global__ void bias_kernel(const float* __restrict__ yrf,
                            const float* __restrict__ brel, const float* __restrict__ barc,
                            float* __restrict__ rrel, float* __restrict__ rarc){
    int y = blockIdx.x, b = blockIdx.y, t = threadIdx.x;
    __shared__ float sy[PK];
    const float* yrow = yrf + ((size_t)b*Yn + y)*PK;
    for (int h = t; h < PK; h += 256) sy[h] = yrow[h];
    __syncthreads();
    int w = t >> 5, lane = t & 31;
    for (int o = w; o < Ln; o += 8){
        const float* wr = brel + (size_t)o*H1n;
        float s = 0.f;
        for (int j = lane; j < Hn; j += 32) s += wr[j]*sy[j];
        #pragma unroll
        for (int off = 16; off; off >>= 1) s += __shfl_xor_sync(0xffffffffu, s, off);
        if (lane == 0) rrel[((size_t)b*Yn + y)*Ln + o] = s + wr[Hn];
    }
    if (w == 0){
        float s = 0.f;
        for (int j = lane; j < Hn; j += 32) s += barc[j]*sy[j];
        #pragma unroll
        for (int off = 16; off; off >>= 1) s += __shfl_xor_sync(0xffffffffu, s, off);
        if (lane == 0) rarc[(size_t)b*Yn + y] = s;
    }
}

// ---------------- transpose / fill / loss ----------------
__global__ void transpose_rel(const float* __restrict__ R, float* __restrict__ out){
    __shared__ float sm[Ln][129];
    int x = blockIdx.x, b = blockIdx.y, y0 = blockIdx.z * 128;
    int t = threadIdx.x;
    for (int i = t; i < Ln*128; i += 256){
        int o = i >> 7, y = i & 127;
        sm[o][y] = R[(((size_t)b*Ln + o)*128 + x)*Yn + y0 + y];
    }
    __syncthreads();
    float* dst = out + ((size_t)(b*Sn + x)*Yn + y0)*Ln;
    for (int i = t; i < 128*Ln; i += 256) dst[i] = sm[i % Ln][i / Ln];
}

__global__ void fill_kernel(const float* __restrict__ rrel, const float* __restrict__ rarc,
                            float* __restrict__ out_rel, float* __restrict__ out_arc){
    int x = 128 + blockIdx.x, b = blockIdx.y, t = threadIdx.x;
    const int YL = Yn*Ln;
    float* dr = out_rel + ((size_t)(b*Sn + x))*YL;
    const float* sr = rrel + (size_t)b*YL;
    for (int i = t; i < YL; i += 256) dr[i] = sr[i];
    float* da = out_arc + ((size_t)(b*Sn + x))*Yn;
    const float* sa = rarc + (size_t)b*Yn;
    for (int i = t; i < Yn; i += 256) da[i] = sa[i];
}

__global__ void loss_kernel(const float* __restrict__ rel, const float* __restrict__ arc,
                            const int* __restrict__ la, const int* __restrict__ lr){
    int x = blockIdx.x, b = blockIdx.y, t = threadIdx.x;
    int lab = la[b*Sn + x];
    if (lab == 0) return;
    int ys = lab; if (ys < 0) ys = 0; if (ys > Yn-1) ys = Yn-1;
    const float* row = arc + ((size_t)(b*Sn + x))*Yn;
    __shared__ float red[256];
    float v = fmaxf(row[t], row[t+256]);
    red[t] = v; __syncthreads();
    for (int s2 = 128; s2 > 0; s2 >>= 1){ if (t < s2) red[t] = fmaxf(red[t], red[t+s2]); __syncthreads(); }
    float mx = red[0]; __syncthreads();
    float e = __expf(row[t]-mx) + __expf(row[t+256]-mx);
    red[t] = e; __syncthreads();
    for (int s2 = 128; s2 > 0; s2 >>= 1){ if (t < s2) red[t] += red[t+s2]; __syncthreads(); }
    float lse = mx + logf(red[0]);
    if (t == 0) atomicAdd(&g_arc_sum, lse - row[ys]);
    __shared__ float rv[Ln];
    const float* rrow = rel + (((size_t)(b*Sn + x))*Yn + ys)*Ln;
    if (t < Ln) rv[t] = rrow[t];
    __syncthreads();
    if (t == 0){
        float m2 = rv[0];
        #pragma unroll
        for (int o = 1; o < Ln; o++) m2 = fmaxf(m2, rv[o]);
        float s = 0.f;
        #pragma unroll
        for (int o = 0; o < Ln; o++) s += __expf(rv[o]-m2);
        int rl = lr[b*Sn + x];
        atomicAdd(&g_rel_sum, -(rv[rl] - m2 - logf(s)));
    }
}

__global__ void finalize_kernel(float* __restrict__ out){
    out[0] = (g_arc_sum + g_rel_sum) / (float)g_n;
}

// ---------------- launch ----------------
extern "C" void kernel_launch(void* const* d_in, const int* in_sizes, int n_in,
                              void* d_out_v, int out_size){
    const float* hidden      = (const float*)d_in[0];
    const float* W_arc       = (const float*)d_in[1];
    const float* W_rel       = (const float*)d_in[2];
    const int*   word_starts = (const int*)d_in[3];
    const int*   labels_arcs = (const int*)d_in[4];
    const int*   labels_rels = (const int*)d_in[5];

    float* out     = (float*)d_out_v;
    float* out_rel = out + 1;
    float* out_arc = out + 1 + (size_t)Bn*Sn*Yn*Ln;

    bf16 *xah,*xal,*yrh,*yrl,*Wrh,*Wrl,*Wah,*Wal,*Th,*Tl,*Uh,*Ul;
    float *xaf,*yrf,*brel,*wcol,*barc,*tcol,*R,*rrel,*rarc;
    cudaGetSymbolAddress((void**)&xah, g_xa_h);  cudaGetSymbolAddress((void**)&xal, g_xa_l);
    cudaGetSymbolAddress((void**)&xaf, g_xaf);
    cudaGetSymbolAddress((void**)&yrh, g_yr_h);  cudaGetSymbolAddress((void**)&yrl, g_yr_l);
    cudaGetSymbolAddress((void**)&yrf, g_yrf);
    cudaGetSymbolAddress((void**)&Wrh, g_Wrt_h); cudaGetSymbolAddress((void**)&Wrl, g_Wrt_l);
    cudaGetSymbolAddress((void**)&Wah, g_Wat_h); cudaGetSymbolAddress((void**)&Wal, g_Wat_l);
    cudaGetSymbolAddress((void**)&brel, g_brel); cudaGetSymbolAddress((void**)&wcol, g_wcol);
    cudaGetSymbolAddress((void**)&barc, g_barc); cudaGetSymbolAddress((void**)&tcol, g_tcol);
    cudaGetSymbolAddress((void**)&Th,  g_T_h);   cudaGetSymbolAddress((void**)&Tl,  g_T_l);
    cudaGetSymbolAddress((void**)&Uh,  g_U_h);   cudaGetSymbolAddress((void**)&Ul,  g_U_l);
    cudaGetSymbolAddress((void**)&R,   g_R);
    cudaGetSymbolAddress((void**)&rrel, g_rrel); cudaGetSymbolAddress((void**)&rarc, g_rarc);

    cudaFuncSetAttribute(mma_gemm<0>, cudaFuncAttributeMaxDynamicSharedMemorySize, SMEM_DYN);
    cudaFuncSetAttribute(mma_gemm<1>, cudaFuncAttributeMaxDynamicSharedMemorySize, SMEM_DYN);
    cudaFuncSetAttribute(mma_gemm<2>, cudaFuncAttributeMaxDynamicSharedMemorySize, SMEM_DYN);

    repack_wrel<<<dim3(24, 24, Ln), 256>>>(W_rel, Wrh, Wrl);
    repack_warc<<<dim3(24, 24), 256>>>(W_arc, Wah, Wal);
    extract_bias<<<Ln + 1, 256>>>(W_rel, W_arc, brel, wcol, barc);
    build_kernel<<<dim3(Sn, Bn), 256>>>(hidden, word_starts, xah, xal, xaf, yrh, yrl, yrf);
    prep_kernel<<<1, 256>>>(labels_arcs);
    tcol_kernel<<<dim3(Ln, Bn), 128>>>(xaf, wcol, tcol);

    // rel1: T[b,o](128x768) = xa[b] @ Wrt[o]^T + 1(x)brel[o] ; z = o*16 + b
    mma_gemm<0><<<dim3(6, 1, Ln*Bn), 256, SMEM_DYN>>>(
        xah, xal, PK, Wrh, Wrl, PK, Th, Tl, nullptr, PK,
        Bn,
        0LL, (ll)128*PK,
        (ll)PK*PK, 0LL,
        (ll)128*PK, (ll)Ln*128*PK,
        brel, (ll)H1n,
        nullptr, 0LL, 0LL);

    // arc1: U[b](128x768) = xa[b] @ Wat^T + 1(x)barc ; z = b
    mma_gemm<0><<<dim3(6, 1, Bn), 256, SMEM_DYN>>>(
        xah, xal, PK, Wah, Wal, PK, Uh, Ul, nullptr, PK,
        1,
        (ll)128*PK, 0LL,
        0LL, 0LL,
        (ll)128*PK, 0LL,
        barc, 0LL,
        nullptr, 0LL, 0LL);

    // rel2: R[b,o](128x512) = T[b,o] @ yr[b]^T + tcol[b,o](x)1 ; z = b*37 + o
    mma_gemm<1><<<dim3(4, 1, Bn*Ln), 256, SMEM_DYN>>>(
        Th, Tl, PK, yrh, yrl, PK, nullptr, nullptr, R, Yn,
        Ln,
        (ll)Ln*128*PK, (ll)128*PK,
        (ll)Yn*PK, 0LL,
        (ll)Ln*128*Yn, (ll)128*Yn,
        nullptr, 0LL,
        tcol, (ll)Ln*128, 128LL);

    // arc2: out_arc[b, x<128, :] = U[b] @ yr[b]^T ; z = b (scalar stores, 4B-aligned dest)
    mma_gemm<2><<<dim3(4, 1, Bn), 256, SMEM_DYN>>>(
        Uh, Ul, PK, yrh, yrl, PK, nullptr, nullptr, out_arc, Yn,
        1,
        (ll)128*PK, 0LL,
        (ll)Yn*PK, 0LL,
        (ll)Sn*Yn, 0LL,
        nullptr, 0LL,
        nullptr, 0LL, 0LL);

    bias_kernel<<<dim3(Yn, Bn), 256>>>(yrf, brel, barc, rrel, rarc);
    transpose_rel<<<dim3(128, Bn, 4), 256>>>(R, out_rel);
    fill_kernel<<<dim3(128, Bn), 256>>>(rrel, rarc, out_rel, out_arc);

    loss_kernel<<<dim3(Sn, Bn), 256>>>(out_rel, out_arc, labels_arcs, labels_rels);
    finalize_kernel<<<1, 1>>>(out);
}

// round 11
// speedup vs baseline: 1.0473x; 1.0473x over previous
#include <cuda_runtime.h>
#include <cuda_bf16.h>
#include <cstdint>
#include <math.h>

#define Bn  16
#define Sn  256
#define Hn  768
#define H1n 769
#define Ln  37
#define Yn  512
#define PK  768      // K (24*32), bias column handled as rank-1 terms
#define KCH 24

typedef long long ll;
typedef unsigned int u32;
typedef __nv_bfloat16 bf16;

#define TILE_B   10240     // 128 rows x 40 bf16 (80B padded rows)
#define STAGE_B  40960
#define SMEM_DYN 81920

// ---------------- static scratch ----------------
__device__ __align__(256) bf16  g_xa_h[(size_t)Bn*128*PK];
__device__ __align__(256) bf16  g_xa_l[(size_t)Bn*128*PK];
__device__ __align__(256) float g_xaf [(size_t)Bn*128*PK];
__device__ __align__(256) bf16  g_yr_h[(size_t)Bn*Yn*PK];
__device__ __align__(256) bf16  g_yr_l[(size_t)Bn*Yn*PK];
__device__ __align__(256) float g_yrf [(size_t)Bn*Yn*PK];
__device__ __align__(256) bf16  g_Wrt_h[(size_t)Ln*PK*PK];
__device__ __align__(256) bf16  g_Wrt_l[(size_t)Ln*PK*PK];
__device__ __align__(256) bf16  g_Wat_h[(size_t)PK*PK];
__device__ __align__(256) bf16  g_Wat_l[(size_t)PK*PK];
__device__ __align__(256) float g_brel[(size_t)Ln*H1n];   // W_rel[o][768][:]
__device__ __align__(256) float g_wcol[(size_t)Ln*H1n];   // W_rel[o][:][768]
__device__ __align__(256) float g_barc[(size_t)Hn];       // W_arc[768][:]
__device__ __align__(256) bf16  g_T_h[(size_t)Bn*Ln*128*PK];
__device__ __align__(256) bf16  g_T_l[(size_t)Bn*Ln*128*PK];
__device__ __align__(256) bf16  g_U_h[(size_t)Bn*128*PK];
__device__ __align__(256) bf16  g_U_l[(size_t)Bn*128*PK];
__device__ __align__(256) float g_tcol[(size_t)Bn*Ln*128];
__device__ __align__(256) float g_R[(size_t)Bn*Ln*128*Yn];
__device__ float g_rrel[(size_t)Bn*Yn*Ln];
__device__ float g_rarc[(size_t)Bn*Yn];
__device__ float g_arc_sum, g_rel_sum;
__device__ int   g_n;

// ---------------- helpers ----------------
__device__ __forceinline__ u32 smem_u32(const void* p){
    u32 a; asm("{ .reg .u64 t; cvta.to.shared.u64 t, %1; cvt.u32.u64 %0, t; }" : "=r"(a) : "l"(p));
    return a;
}
__device__ __forceinline__ void ldsm4(u32* d, u32 addr){
    asm volatile("ldmatrix.sync.aligned.m8n8.x4.shared.b16 {%0,%1,%2,%3}, [%4];"
        : "=r"(d[0]), "=r"(d[1]), "=r"(d[2]), "=r"(d[3]) : "r"(addr));
}
__device__ __forceinline__ void mma16816(float* c, const u32* a, u32 b0, u32 b1){
    asm volatile("mma.sync.aligned.m16n8k16.row.col.f32.bf16.bf16.f32 "
        "{%0,%1,%2,%3}, {%4,%5,%6,%7}, {%8,%9}, {%0,%1,%2,%3};"
        : "+f"(c[0]), "+f"(c[1]), "+f"(c[2]), "+f"(c[3])
        : "r"(a[0]), "r"(a[1]), "r"(a[2]), "r"(a[3]), "r"(b0), "r"(b1));
}
__device__ __forceinline__ void cpasync16(u32 dst, const void* src){
    asm volatile("cp.async.cg.shared.global [%0], [%1], 16;" :: "r"(dst), "l"(src) : "memory");
}
#define CP_COMMIT() asm volatile("cp.async.commit_group;" ::: "memory")
#define CP_WAIT0()  asm volatile("cp.async.wait_group 0;" ::: "memory")

__device__ __forceinline__ void split2(float f0, float f1, u32& hp, u32& lp){
    u32 h;
    asm("cvt.rn.bf16x2.f32 %0, %1, %2;" : "=r"(h) : "f"(f1), "f"(f0));
    float h0 = __uint_as_float(h << 16);
    float h1 = __uint_as_float(h & 0xffff0000u);
    asm("cvt.rn.bf16x2.f32 %0, %1, %2;" : "=r"(lp) : "f"(f1 - h1), "f"(f0 - h0));
    hp = h;
}

// ---------------- weight repack: transpose + split (768x768 exact) ----------------
__global__ void repack_wrel(const float* __restrict__ W, bf16* __restrict__ Wh, bf16* __restrict__ Wl){
    __shared__ float sm[32][33];
    int o = blockIdx.z, i0 = blockIdx.x*32, j0 = blockIdx.y*32;
    int tx = threadIdx.x & 31, ty = threadIdx.x >> 5;
    for (int r = ty; r < 32; r += 8)
        sm[r][tx] = W[((size_t)o*H1n + i0 + r)*H1n + j0 + tx];
    __syncthreads();
    for (int r = ty; r < 32; r += 8){
        int j = j0 + r, i = i0 + tx;
        float v = sm[tx][r];
        bf16 h = __float2bfloat16_rn(v);
        size_t d = ((size_t)o*PK + j)*PK + i;
        Wh[d] = h; Wl[d] = __float2bfloat16_rn(v - __bfloat162float(h));
    }
}
__global__ void repack_warc(const float* __restrict__ W, bf16* __restrict__ Wh, bf16* __restrict__ Wl){
    __shared__ float sm[32][33];
    int i0 = blockIdx.x*32, j0 = blockIdx.y*32;
    int tx = threadIdx.x & 31, ty = threadIdx.x >> 5;
    for (int r = ty; r < 32; r += 8)
        sm[r][tx] = W[(size_t)(i0 + r)*Hn + j0 + tx];
    __syncthreads();
    for (int r = ty; r < 32; r += 8){
        int j = j0 + r, i = i0 + tx;
        float v = sm[tx][r];
        bf16 h = __float2bfloat16_rn(v);
        size_t d = (size_t)j*PK + i;
        Wh[d] = h; Wl[d] = __float2bfloat16_rn(v - __bfloat162float(h));
    }
}

// extract bias rows/cols
__global__ void extract_bias(const float* __restrict__ Wrel, const float* __restrict__ Warc,
                             float* __restrict__ brel, float* __restrict__ wcol, float* __restrict__ barc){
    int o = blockIdx.x, t = threadIdx.x;
    if (o < Ln){
        for (int j = t; j < H1n; j += 256){
            brel[(size_t)o*H1n + j] = Wrel[((size_t)o*H1n + Hn)*H1n + j];
            wcol[(size_t)o*H1n + j] = Wrel[((size_t)o*H1n + j)*H1n + Hn];
        }
    } else {
        for (int j = t; j < Hn; j += 256) barc[j] = Warc[(size_t)Hn*Hn + j];
    }
}

// ---------------- build xa/yr (segment mean, split, K=768) ----------------
__global__ void build_kernel(const float* __restrict__ hidden, const int* __restrict__ ws,
                             bf16* __restrict__ xah, bf16* __restrict__ xal, float* __restrict__ xaf,
                             bf16* __restrict__ yrh, bf16* __restrict__ yrl, float* __restrict__ yrf){
    int j = blockIdx.x, b = blockIdx.y, t = threadIdx.x;
    __shared__ int sws[Sn];
    int myws = ws[b*Sn + t];
    sws[t] = myws;
    int n_valid = __syncthreads_count(myws != 0);
    int start = sws[j];
    int end = (j+1 < Sn) ? sws[j+1] : 0;
    bool valid = (j+1) < n_valid;
    int len = end - start; if (len < 1) len = 1;
    float inv = 1.0f/(float)len;
    const float* hb = hidden + (size_t)b*Sn*Hn;
    size_t yj = ((size_t)b*Yn + j)*PK;
    size_t yd = ((size_t)b*Yn + Sn + j)*PK;
    size_t xj = ((size_t)b*128 + j)*PK;
    for (int h = t; h < PK; h += 256){
        float hv = hb[(size_t)j*Hn + h];
        float dv = 0.f;
        if (valid){
            float s = 0.f;
            for (int tok = start; tok < end; ++tok) s += hb[(size_t)tok*Hn + h];
            dv = s*inv;
        }
        bf16 hh = __float2bfloat16_rn(hv);
        bf16 dh = __float2bfloat16_rn(dv);
        yrh[yj+h] = hh; yrl[yj+h] = __float2bfloat16_rn(hv - __bfloat162float(hh));
        yrf[yj+h] = hv;
        yrh[yd+h] = dh; yrl[yd+h] = __float2bfloat16_rn(dv - __bfloat162float(dh));
        yrf[yd+h] = dv;
        if (j < 128){
            xah[xj+h] = dh; xal[xj+h] = __float2bfloat16_rn(dv - __bfloat162float(dh));
            xaf[xj+h] = dv;
        }
    }
}

__global__ void prep_kernel(const int* __restrict__ la){
    int t = threadIdx.x, cnt = 0;
    for (int i = t; i < Bn*Sn; i += 256) cnt += (la[i] != 0);
    __shared__ int sc[256];
    sc[t] = cnt; __syncthreads();
    for (int s2 = 128; s2 > 0; s2 >>= 1){ if (t < s2) sc[t] += sc[t+s2]; __syncthreads(); }
    if (t == 0){ g_n = sc[0]; g_arc_sum = 0.f; g_rel_sum = 0.f; }
}

// tcol[b][o][x] = dot(xaf[b][x], wcol[o][0..767]) + wcol[o][768]
__global__ void tcol_kernel(const float* __restrict__ xaf, const float* __restrict__ wcol,
                            float* __restrict__ tcol){
    int o = blockIdx.x, b = blockIdx.y;
    int t = threadIdx.x;
    __shared__ float sw[PK];
    for (int i = t; i < PK; i += 128) sw[i] = wcol[(size_t)o*H1n + i];
    __syncthreads();
    const float* xr = xaf + ((size_t)b*128 + t)*PK;
    float s = wcol[(size_t)o*H1n + Hn];
    #pragma unroll 4
    for (int i = 0; i < PK; i += 4){
        float4 xv = *(const float4*)(xr + i);
        s += xv.x*sw[i] + xv.y*sw[i+1] + xv.z*sw[i+2] + xv.w*sw[i+3];
    }
    tcol[((size_t)b*Ln + o)*128 + t] = s;
}

// ---------------- HMMA GEMM, cp.async 2-stage, frag-reuse 3-pass, 2 CTAs/SM ----------------
template<int EPI>
__global__ void __launch_bounds__(256, 2)
mma_gemm(const bf16* __restrict__ Ah, const bf16* __restrict__ Al, ll lda,
         const bf16* __restrict__ Bh, const bf16* __restrict__ Bl, ll ldb,
         bf16* __restrict__ Ch, bf16* __restrict__ Cl, float* __restrict__ Cf, ll ldc,
         int P, ll pA, ll qA, ll pB, ll qB, ll pC, ll qC,
         const float* __restrict__ bias, ll pBias,
         const float* __restrict__ rowadd, ll pRow, ll qRow){
    extern __shared__ char smem[];
    const u32 sb = smem_u32(smem);

    const int tid = threadIdx.x;
    const int lane = tid & 31, wid = tid >> 5;
    const int wm = wid & 1, wn = wid >> 1;

    int z = blockIdx.z, zp = z / P, zq = z - zp*P;
    int col0 = blockIdx.x * 128;
    const bf16* A0h = Ah + (size_t)(zp*pA + zq*qA);
    const bf16* A0l = Al + (size_t)(zp*pA + zq*qA);
    const bf16* B0h = Bh + (size_t)(zp*pB + zq*qB) + (size_t)col0*ldb;
    const bf16* B0l = Bl + (size_t)(zp*pB + zq*qB) + (size_t)col0*ldb;

    const int cr0 = tid >> 2;
    const int cs  = tid & 3;
    auto issue = [&](int c){
        int k0 = c * 32;
        const bf16* s0 = A0h + k0; const bf16* s1 = A0l + k0;
        const bf16* s2 = B0h + k0; const bf16* s3 = B0l + k0;
        u32 base = sb + (u32)(c & 1) * STAGE_B;
        #pragma unroll
        for (int rep = 0; rep < 2; rep++){
            int row = cr0 + rep*64;
            u32 doff = (u32)(row*80 + cs*16);
            cpasync16(base + 0*TILE_B + doff, s0 + (size_t)row*lda + cs*8);
            cpasync16(base + 1*TILE_B + doff, s1 + (size_t)row*lda + cs*8);
            cpasync16(base + 2*TILE_B + doff, s2 + (size_t)row*ldb + cs*8);
            cpasync16(base + 3*TILE_B + doff, s3 + (size_t)row*ldb + cs*8);
        }
        CP_COMMIT();
    };

    float acc[4][4][4];
    #pragma unroll
    for (int i = 0; i < 4; i++)
        #pragma unroll
        for (int j = 0; j < 4; j++)
            #pragma unroll
            for (int k = 0; k < 4; k++) acc[i][j][k] = 0.f;

    const int arow = wm*64 + (lane & 15);
    const int aseg = (lane >> 4) * 8;
    const int bg   = lane >> 3;
    const int brow_in = (lane & 7);
    const int brow_base = wn*32 + ((bg >> 1) << 3) + brow_in;
    const int bseg = (bg & 1) * 8;

    issue(0);

    #pragma unroll 1
    for (int c = 0; c < KCH; ++c){
        CP_WAIT0();
        __syncthreads();
        if (c + 1 < KCH) issue(c + 1);

        u32 sbase = sb + (u32)(c & 1) * STAGE_B;
        #pragma unroll
        for (int ks = 0; ks < 2; ks++){
            u32 ah[4][4], al[4][4];
            u32 bh[2][4], blf[2][4];
            #pragma unroll
            for (int mi = 0; mi < 4; mi++)
                ldsm4(ah[mi], sbase + (u32)((arow + mi*16)*40 + ks*16 + aseg)*2u);
            #pragma unroll
            for (int nh = 0; nh < 2; nh++)
                ldsm4(bh[nh], sbase + 2u*TILE_B + (u32)((brow_base + nh*16)*40 + ks*16 + bseg)*2u);
            #pragma unroll
            for (int nh = 0; nh < 2; nh++)
                ldsm4(blf[nh], sbase + 3u*TILE_B + (u32)((brow_base + nh*16)*40 + ks*16 + bseg)*2u);
            #pragma unroll
            for (int mi = 0; mi < 4; mi++)
                ldsm4(al[mi], sbase + TILE_B + (u32)((arow + mi*16)*40 + ks*16 + aseg)*2u);

            #pragma unroll
            for (int mi = 0; mi < 4; mi++)
                #pragma unroll
                for (int ni = 0; ni < 4; ni++)
                    mma16816(acc[mi][ni], ah[mi], bh[ni>>1][(ni&1)*2], bh[ni>>1][(ni&1)*2+1]);
            #pragma unroll
            for (int mi = 0; mi < 4; mi++)
                #pragma unroll
                for (int ni = 0; ni < 4; ni++)
                    mma16816(acc[mi][ni], ah[mi], blf[ni>>1][(ni&1)*2], blf[ni>>1][(ni&1)*2+1]);
            #pragma unroll
            for (int mi = 0; mi < 4; mi++)
                #pragma unroll
                for (int ni = 0; ni < 4; ni++)
                    mma16816(acc[mi][ni], al[mi], bh[ni>>1][(ni&1)*2], bh[ni>>1][(ni&1)*2+1]);
        }
    }

    ll cofs = (ll)zp*pC + (ll)zq*qC;
    const float* bp = (EPI == 0) ? (bias + zp*pBias) : nullptr;
    const float* rp = (EPI == 1) ? (rowadd + zp*pRow + zq*qRow) : nullptr;

    #pragma unroll
    for (int mi = 0; mi < 4; mi++){
        int rr = wm*64 + mi*16 + (lane >> 2);
        #pragma unroll
        for (int ni = 0; ni < 4; ni++){
            int cc = col0 + wn*32 + ni*8 + (lane & 3)*2;
            float* cr = acc[mi][ni];
            if (EPI == 0){
                float bv0 = bp[cc], bv1 = bp[cc+1];
                u32 h0, l0, h1, l1;
                split2(cr[0]+bv0, cr[1]+bv1, h0, l0);
                split2(cr[2]+bv0, cr[3]+bv1, h1, l1);
                *(u32*)(Ch + cofs + (size_t)rr*ldc + cc)     = h0;
                *(u32*)(Cl + cofs + (size_t)rr*ldc + cc)     = l0;
                *(u32*)(Ch + cofs + (size_t)(rr+8)*ldc + cc) = h1;
                *(u32*)(Cl + cofs + (size_t)(rr+8)*ldc + cc) = l1;
            } else if (EPI == 1){
                float r0 = rp[rr], r1 = rp[rr+8];
                *(float2*)(Cf + cofs + (size_t)rr*ldc + cc)     = make_float2(cr[0]+r0, cr[1]+r0);
                *(float2*)(Cf + cofs + (size_t)(rr+8)*ldc + cc) = make_float2(cr[2]+r1, cr[3]+r1);
            } else {
                float* p0 = Cf + cofs + (size_t)rr*ldc + cc;
                float* p1 = Cf + cofs + (size_t)(rr+8)*ldc + cc;
                p0[0] = cr[0]; p0[1] = cr[1];
                p1[0] = cr[2]; p1[1] = cr[3];
            }
        }
    }
}

// ---------------- bias rows (exact fp32) ----------------
__global__ void bias_kernel(const float* __restrict__ yrf,
                            const float* __restrict__ brel, const float* __restrict__ barc,
                            float* __restrict__ rrel, float* __restrict__ rarc){
    int y = blockIdx.x, b = blockIdx.y, t = threadIdx.x;
    __shared__ float sy[PK];
    const float* yrow = yrf + ((size_t)b*Yn + y)*PK;
    for (int h = t; h < PK; h += 256) sy[h] = yrow[h];
    __syncthreads();
    int w = t >> 5, lane = t & 31;
    for (int o = w; o < Ln; o += 8){
        const float* wr = brel + (size_t)o*H1n;
        float s = 0.f;
        for (int j = lane; j < Hn; j += 32) s += wr[j]*sy[j];
        #pragma unroll
        for (int off = 16; off; off >>= 1) s += __shfl_xor_sync(0xffffffffu, s, off);
        if (lane == 0) rrel[((size_t)b*Yn + y)*Ln + o] = s + wr[Hn];
    }
    if (w == 0){
        float s = 0.f;
        for (int j = lane; j < Hn; j += 32) s += barc[j]*sy[j];
        #pragma unroll
        for (int off = 16; off; off >>= 1) s += __shfl_xor_sync(0xffffffffu, s, off);
        if (lane == 0) rarc[(size_t)b*Yn + y] = s;
    }
}

// ---------------- transpose / fill / loss ----------------
__global__ void transpose_rel(const float* __restrict__ R, float* __restrict__ out){
    __shared__ float sm[Ln][129];
    int x = blockIdx.x, b = blockIdx.y, y0 = blockIdx.z * 128;
    int t = threadIdx.x;
    for (int i = t; i < Ln*128; i += 256){
        int o = i >> 7, y = i & 127;
        sm[o][y] = R[(((size_t)b*Ln + o)*128 + x)*Yn + y0 + y];
    }
    __syncthreads();
    float* dst = out + ((size_t)(b*Sn + x)*Yn + y0)*Ln;
    for (int i = t; i < 128*Ln; i += 256) dst[i] = sm[i % Ln][i / Ln];
}

__global__ void fill_kernel(const float* __restrict__ rrel, const float* __restrict__ rarc,
                            float* __restrict__ out_rel, float* __restrict__ out_arc){
    int x = 128 + blockIdx.x, b = blockIdx.y, t = threadIdx.x;
    const int YL = Yn*Ln;
    float* dr = out_rel + ((size_t)(b*Sn + x))*YL;
    const float* sr = rrel + (size_t)b*YL;
    for (int i = t; i < YL; i += 256) dr[i] = sr[i];
    float* da = out_arc + ((size_t)(b*Sn + x))*Yn;
    const float* sa = rarc + (size_t)b*Yn;
    for (int i = t; i < Yn; i += 256) da[i] = sa[i];
}

__global__ void loss_kernel(const float* __restrict__ rel, const float* __restrict__ arc,
                            const int* __restrict__ la, const int* __restrict__ lr){
    int x = blockIdx.x, b = blockIdx.y, t = threadIdx.x;
    int lab = la[b*Sn + x];
    if (lab == 0) return;
    int ys = lab; if (ys < 0) ys = 0; if (ys > Yn-1) ys = Yn-1;
    const float* row = arc + ((size_t)(b*Sn + x))*Yn;
    __shared__ float red[256];
    float v = fmaxf(row[t], row[t+256]);
    red[t] = v; __syncthreads();
    for (int s2 = 128; s2 > 0; s2 >>= 1){ if (t < s2) red[t] = fmaxf(red[t], red[t+s2]); __syncthreads(); }
    float mx = red[0]; __syncthreads();
    float e = __expf(row[t]-mx) + __expf(row[t+256]-mx);
    red[t] = e; __syncthreads();
    for (int s2 = 128; s2 > 0; s2 >>= 1){ if (t < s2) red[t] += red[t+s2]; __syncthreads(); }
    float lse = mx + logf(red[0]);
    if (t == 0) atomicAdd(&g_arc_sum, lse - row[ys]);
    __shared__ float rv[Ln];
    const float* rrow = rel + (((size_t)(b*Sn + x))*Yn + ys)*Ln;
    if (t < Ln) rv[t] = rrow[t];
    __syncthreads();
    if (t == 0){
        float m2 = rv[0];
        #pragma unroll
        for (int o = 1; o < Ln; o++) m2 = fmaxf(m2, rv[o]);
        float s = 0.f;
        #pragma unroll
        for (int o = 0; o < Ln; o++) s += __expf(rv[o]-m2);
        int rl = lr[b*Sn + x];
        atomicAdd(&g_rel_sum, -(rv[rl] - m2 - logf(s)));
    }
}

__global__ void finalize_kernel(float* __restrict__ out){
    out[0] = (g_arc_sum + g_rel_sum) / (float)g_n;
}

// ---------------- launch ----------------
extern "C" void kernel_launch(void* const* d_in, const int* in_sizes, int n_in,
                              void* d_out_v, int out_size){
    const float* hidden      = (const float*)d_in[0];
    const float* W_arc       = (const float*)d_in[1];
    const float* W_rel       = (const float*)d_in[2];
    const int*   word_starts = (const int*)d_in[3];
    const int*   labels_arcs = (const int*)d_in[4];
    const int*   labels_rels = (const int*)d_in[5];

    float* out     = (float*)d_out_v;
    float* out_rel = out + 1;
    float* out_arc = out + 1 + (size_t)Bn*Sn*Yn*Ln;

    bf16 *xah,*xal,*yrh,*yrl,*Wrh,*Wrl,*Wah,*Wal,*Th,*Tl,*Uh,*Ul;
    float *xaf,*yrf,*brel,*wcol,*barc,*tcol,*R,*rrel,*rarc;
    cudaGetSymbolAddress((void**)&xah, g_xa_h);  cudaGetSymbolAddress((void**)&xal, g_xa_l);
    cudaGetSymbolAddress((void**)&xaf, g_xaf);
    cudaGetSymbolAddress((void**)&yrh, g_yr_h);  cudaGetSymbolAddress((void**)&yrl, g_yr_l);
    cudaGetSymbolAddress((void**)&yrf, g_yrf);
    cudaGetSymbolAddress((void**)&Wrh, g_Wrt_h); cudaGetSymbolAddress((void**)&Wrl, g_Wrt_l);
    cudaGetSymbolAddress((void**)&Wah, g_Wat_h); cudaGetSymbolAddress((void**)&Wal, g_Wat_l);
    cudaGetSymbolAddress((void**)&brel, g_brel); cudaGetSymbolAddress((void**)&wcol, g_wcol);
    cudaGetSymbolAddress((void**)&barc, g_barc); cudaGetSymbolAddress((void**)&tcol, g_tcol);
    cudaGetSymbolAddress((void**)&Th,  g_T_h);   cudaGetSymbolAddress((void**)&Tl,  g_T_l);
    cudaGetSymbolAddress((void**)&Uh,  g_U_h);   cudaGetSymbolAddress((void**)&Ul,  g_U_l);
    cudaGetSymbolAddress((void**)&R,   g_R);
    cudaGetSymbolAddress((void**)&rrel, g_rrel); cudaGetSymbolAddress((void**)&rarc, g_rarc);

    cudaFuncSetAttribute(mma_gemm<0>, cudaFuncAttributeMaxDynamicSharedMemorySize, SMEM_DYN);
    cudaFuncSetAttribute(mma_gemm<1>, cudaFuncAttributeMaxDynamicSharedMemorySize, SMEM_DYN);
    cudaFuncSetAttribute(mma_gemm<2>, cudaFuncAttributeMaxDynamicSharedMemorySize, SMEM_DYN);

    // side stream + events for the independent arc/bias/fill chain (created once;
    // fork/join via events is the supported stream-capture pattern)
    static cudaStream_t s2 = nullptr;
    static cudaEvent_t evA = nullptr, evB = nullptr;
    if (!s2){
        cudaStreamCreateWithFlags(&s2, cudaStreamNonBlocking);
        cudaEventCreateWithFlags(&evA, cudaEventDisableTiming);
        cudaEventCreateWithFlags(&evB, cudaEventDisableTiming);
    }

    // ---- main stream: launches 1..5, then rel1 as launch #6 (ncu -s 5 -c 1) ----
    extract_bias<<<Ln + 1, 256>>>(W_rel, W_arc, brel, wcol, barc);                    // 1
    build_kernel<<<dim3(Sn, Bn), 256>>>(hidden, word_starts, xah, xal, xaf, yrh, yrl, yrf); // 2
    prep_kernel<<<1, 256>>>(labels_arcs);                                             // 3
    tcol_kernel<<<dim3(Ln, Bn), 128>>>(xaf, wcol, tcol);                              // 4
    repack_wrel<<<dim3(24, 24, Ln), 256>>>(W_rel, Wrh, Wrl);                          // 5

    cudaEventRecord(evA, 0);   // fork point: build/extract results ready (stream-ordered)

    // rel1: T[b,o](128x768) = xa[b] @ Wrt[o]^T + 1(x)brel[o] ; z = o*16 + b    (launch #6)
    mma_gemm<0><<<dim3(6, 1, Ln*Bn), 256, SMEM_DYN>>>(
        xah, xal, PK, Wrh, Wrl, PK, Th, Tl, nullptr, PK,
        Bn,
        0LL, (ll)128*PK,
        (ll)PK*PK, 0LL,
        (ll)128*PK, (ll)Ln*128*PK,
        brel, (ll)H1n,
        nullptr, 0LL, 0LL);

    // rel2: R[b,o](128x512) = T[b,o] @ yr[b]^T + tcol[b,o](x)1 ; z = b*37 + o
    mma_gemm<1><<<dim3(4, 1, Bn*Ln), 256, SMEM_DYN>>>(
        Th, Tl, PK, yrh, yrl, PK, nullptr, nullptr, R, Yn,
        Ln,
        (ll)Ln*128*PK, (ll)128*PK,
        (ll)Yn*PK, 0LL,
        (ll)Ln*128*Yn, (ll)128*Yn,
        nullptr, 0LL,
        tcol, (ll)Ln*128, 128LL);

    transpose_rel<<<dim3(128, Bn, 4), 256>>>(R, out_rel);

    // ---- side stream: arc chain + bias/fill, overlapped with rel GEMMs ----
    cudaStreamWaitEvent(s2, evA, 0);
    repack_warc<<<dim3(24, 24), 256, 0, s2>>>(W_arc, Wah, Wal);
    mma_gemm<0><<<dim3(6, 1, Bn), 256, SMEM_DYN, s2>>>(
        xah, xal, PK, Wah, Wal, PK, Uh, Ul, nullptr, PK,
        1,
        (ll)128*PK, 0LL,
        0LL, 0LL,
        (ll)128*PK, 0LL,
        barc, 0LL,
        nullptr, 0LL, 0LL);
    mma_gemm<2><<<dim3(4, 1, Bn), 256, SMEM_DYN, s2>>>(
        Uh, Ul, PK, yrh, yrl, PK, nullptr, nullptr, out_arc, Yn,
        1,
        (ll)128*PK, 0LL,
        (ll)Yn*PK, 0LL,
        (ll)Sn*Yn, 0LL,
        nullptr, 0LL,
        nullptr, 0LL, 0LL);
    bias_kernel<<<dim3(Yn, Bn), 256, 0, s2>>>(yrf, brel, barc, rrel, rarc);
    fill_kernel<<<dim3(128, Bn), 256, 0, s2>>>(rrel, rarc, out_rel, out_arc);
    cudaEventRecord(evB, s2);

    // ---- join, then loss ----
    cudaStreamWaitEvent(0, evB, 0);
    loss_kernel<<<dim3(Sn, Bn), 256>>>(out_rel, out_arc, labels_arcs, labels_rels);
    finalize_kernel<<<1, 1>>>(out);
}

// round 13
// speedup vs baseline: 1.0536x; 1.0061x over previous
#include <cuda_runtime.h>
#include <cuda_bf16.h>
#include <cstdint>
#include <math.h>

#define Bn  16
#define Sn  256
#define Hn  768
#define H1n 769
#define Ln  37
#define Yn  512
#define PK  768
#define KCH 24

typedef long long ll;
typedef unsigned int u32;
typedef __nv_bfloat16 bf16;

#define TILE_B   10240
#define STAGE_B  40960
#define SMEM_DYN 81920

// ---------------- static scratch ----------------
__device__ __align__(256) bf16  g_xa_h[(size_t)Bn*128*PK];
__device__ __align__(256) bf16  g_xa_l[(size_t)Bn*128*PK];
__device__ __align__(256) float g_xaf [(size_t)Bn*128*PK];
__device__ __align__(256) bf16  g_yr_h[(size_t)Bn*Yn*PK];
__device__ __align__(256) bf16  g_yr_l[(size_t)Bn*Yn*PK];
__device__ __align__(256) float g_yrf [(size_t)Bn*Yn*PK];
__device__ __align__(256) bf16  g_Wrt_h[(size_t)Ln*PK*PK];
__device__ __align__(256) bf16  g_Wrt_l[(size_t)Ln*PK*PK];
__device__ __align__(256) bf16  g_Wat_h[(size_t)PK*PK];
__device__ __align__(256) bf16  g_Wat_l[(size_t)PK*PK];
__device__ __align__(256) float g_brel[(size_t)Ln*H1n];
__device__ __align__(256) float g_wcol[(size_t)Ln*H1n];
__device__ __align__(256) float g_barc[(size_t)Hn];
__device__ __align__(256) bf16  g_T_h[(size_t)Bn*Ln*128*PK];
__device__ __align__(256) bf16  g_T_l[(size_t)Bn*Ln*128*PK];
__device__ __align__(256) bf16  g_U_h[(size_t)Bn*128*PK];
__device__ __align__(256) bf16  g_U_l[(size_t)Bn*128*PK];
__device__ __align__(256) float g_tcol[(size_t)Bn*Ln*128];
__device__ __align__(256) float g_R[(size_t)Bn*Ln*128*Yn];
__device__ float g_rrel[(size_t)Bn*Yn*Ln];
__device__ float g_rarc[(size_t)Bn*Yn];
__device__ float g_arc_sum, g_rel_sum;
__device__ int   g_n;

// ---------------- helpers ----------------
__device__ __forceinline__ u32 smem_u32(const void* p){
    u32 a; asm("{ .reg .u64 t; cvta.to.shared.u64 t, %1; cvt.u32.u64 %0, t; }" : "=r"(a) : "l"(p));
    return a;
}
__device__ __forceinline__ void ldsm4(u32* d, u32 addr){
    asm volatile("ldmatrix.sync.aligned.m8n8.x4.shared.b16 {%0,%1,%2,%3}, [%4];"
        : "=r"(d[0]), "=r"(d[1]), "=r"(d[2]), "=r"(d[3]) : "r"(addr));
}
__device__ __forceinline__ void mma16816(float* c, const u32* a, u32 b0, u32 b1){
    asm volatile("mma.sync.aligned.m16n8k16.row.col.f32.bf16.bf16.f32 "
        "{%0,%1,%2,%3}, {%4,%5,%6,%7}, {%8,%9}, {%0,%1,%2,%3};"
        : "+f"(c[0]), "+f"(c[1]), "+f"(c[2]), "+f"(c[3])
        : "r"(a[0]), "r"(a[1]), "r"(a[2]), "r"(a[3]), "r"(b0), "r"(b1));
}
__device__ __forceinline__ void cpasync16(u32 dst, const void* src){
    asm volatile("cp.async.cg.shared.global [%0], [%1], 16;" :: "r"(dst), "l"(src) : "memory");
}
#define CP_COMMIT() asm volatile("cp.async.commit_group;" ::: "memory")
#define CP_WAIT0()  asm volatile("cp.async.wait_group 0;" ::: "memory")

__device__ __forceinline__ void split2(float f0, float f1, u32& hp, u32& lp){
    u32 h;
    asm("cvt.rn.bf16x2.f32 %0, %1, %2;" : "=r"(h) : "f"(f1), "f"(f0));
    float h0 = __uint_as_float(h << 16);
    float h1 = __uint_as_float(h & 0xffff0000u);
    asm("cvt.rn.bf16x2.f32 %0, %1, %2;" : "=r"(lp) : "f"(f1 - h1), "f"(f0 - h0));
    hp = h;
}

// ---------------- weight repack: transpose + split ----------------
__global__ void repack_wrel(const float* __restrict__ W, bf16* __restrict__ Wh, bf16* __restrict__ Wl){
    __shared__ float sm[32][33];
    int o = blockIdx.z, i0 = blockIdx.x*32, j0 = blockIdx.y*32;
    int tx = threadIdx.x & 31, ty = threadIdx.x >> 5;
    for (int r = ty; r < 32; r += 8)
        sm[r][tx] = W[((size_t)o*H1n + i0 + r)*H1n + j0 + tx];
    __syncthreads();
    for (int r = ty; r < 32; r += 8){
        int j = j0 + r, i = i0 + tx;
        float v = sm[tx][r];
        bf16 h = __float2bfloat16_rn(v);
        size_t d = ((size_t)o*PK + j)*PK + i;
        Wh[d] = h; Wl[d] = __float2bfloat16_rn(v - __bfloat162float(h));
    }
}
__global__ void repack_warc(const float* __restrict__ W, bf16* __restrict__ Wh, bf16* __restrict__ Wl){
    __shared__ float sm[32][33];
    int i0 = blockIdx.x*32, j0 = blockIdx.y*32;
    int tx = threadIdx.x & 31, ty = threadIdx.x >> 5;
    for (int r = ty; r < 32; r += 8)
        sm[r][tx] = W[(size_t)(i0 + r)*Hn + j0 + tx];
    __syncthreads();
    for (int r = ty; r < 32; r += 8){
        int j = j0 + r, i = i0 + tx;
        float v = sm[tx][r];
        bf16 h = __float2bfloat16_rn(v);
        size_t d = (size_t)j*PK + i;
        Wh[d] = h; Wl[d] = __float2bfloat16_rn(v - __bfloat162float(h));
    }
}

__global__ void extract_bias(const float* __restrict__ Wrel, const float* __restrict__ Warc,
                             float* __restrict__ brel, float* __restrict__ wcol, float* __restrict__ barc){
    int o = blockIdx.x, t = threadIdx.x;
    if (o < Ln){
        for (int j = t; j < H1n; j += 256){
            brel[(size_t)o*H1n + j] = Wrel[((size_t)o*H1n + Hn)*H1n + j];
            wcol[(size_t)o*H1n + j] = Wrel[((size_t)o*H1n + j)*H1n + Hn];
        }
    } else {
        for (int j = t; j < Hn; j += 256) barc[j] = Warc[(size_t)Hn*Hn + j];
    }
}

// ---------------- build xa/yr ----------------
__global__ void build_kernel(const float* __restrict__ hidden, const int* __restrict__ ws,
                             bf16* __restrict__ xah, bf16* __restrict__ xal, float* __restrict__ xaf,
                             bf16* __restrict__ yrh, bf16* __restrict__ yrl, float* __restrict__ yrf){
    int j = blockIdx.x, b = blockIdx.y, t = threadIdx.x;
    __shared__ int sws[Sn];
    int myws = ws[b*Sn + t];
    sws[t] = myws;
    int n_valid = __syncthreads_count(myws != 0);
    int start = sws[j];
    int end = (j+1 < Sn) ? sws[j+1] : 0;
    bool valid = (j+1) < n_valid;
    int len = end - start; if (len < 1) len = 1;
    float inv = 1.0f/(float)len;
    const float* hb = hidden + (size_t)b*Sn*Hn;
    size_t yj = ((size_t)b*Yn + j)*PK;
    size_t yd = ((size_t)b*Yn + Sn + j)*PK;
    size_t xj = ((size_t)b*128 + j)*PK;
    for (int h = t; h < PK; h += 256){
        float hv = hb[(size_t)j*Hn + h];
        float dv = 0.f;
        if (valid){
            float s = 0.f;
            for (int tok = start; tok < end; ++tok) s += hb[(size_t)tok*Hn + h];
            dv = s*inv;
        }
        bf16 hh = __float2bfloat16_rn(hv);
        bf16 dh = __float2bfloat16_rn(dv);
        yrh[yj+h] = hh; yrl[yj+h] = __float2bfloat16_rn(hv - __bfloat162float(hh));
        yrf[yj+h] = hv;
        yrh[yd+h] = dh; yrl[yd+h] = __float2bfloat16_rn(dv - __bfloat162float(dh));
        yrf[yd+h] = dv;
        if (j < 128){
            xah[xj+h] = dh; xal[xj+h] = __float2bfloat16_rn(dv - __bfloat162float(dh));
            xaf[xj+h] = dv;
        }
    }
}

__global__ void prep_kernel(const int* __restrict__ la){
    int t = threadIdx.x, cnt = 0;
    for (int i = t; i < Bn*Sn; i += 256) cnt += (la[i] != 0);
    __shared__ int sc[256];
    sc[t] = cnt; __syncthreads();
    for (int s2 = 128; s2 > 0; s2 >>= 1){ if (t < s2) sc[t] += sc[t+s2]; __syncthreads(); }
    if (t == 0){ g_n = sc[0]; g_arc_sum = 0.f; g_rel_sum = 0.f; }
}

// tcol[b][o][x] = dot(xaf[b][x], wcol[o][:768]) + wcol[o][768]  (warp-per-row, coalesced)
__global__ void tcol_kernel(const float* __restrict__ xaf, const float* __restrict__ wcol,
                            float* __restrict__ tcol){
    int o = blockIdx.x, b = blockIdx.y;
    int t = threadIdx.x, w = t >> 5, lane = t & 31;
    __shared__ float sw[PK];
    for (int i = t; i < PK; i += 256) sw[i] = wcol[(size_t)o*H1n + i];
    __syncthreads();
    float cbias = wcol[(size_t)o*H1n + Hn];
    for (int x = w; x < 128; x += 8){
        const float* xr = xaf + ((size_t)b*128 + x)*PK;
        float s = 0.f;
        #pragma unroll 4
        for (int i = lane; i < PK; i += 32) s += xr[i]*sw[i];
        #pragma unroll
        for (int off = 16; off; off >>= 1) s += __shfl_xor_sync(0xffffffffu, s, off);
        if (lane == 0) tcol[((size_t)b*Ln + o)*128 + x] = s + cbias;
    }
}

// ---------------- HMMA GEMM, cp.async 2-stage, frag-reuse 3-pass, 2 CTAs/SM ----------------
template<int EPI>
__global__ void __launch_bounds__(256, 2)
mma_gemm(const bf16* __restrict__ Ah, const bf16* __restrict__ Al, ll lda,
         const bf16* __restrict__ Bh, const bf16* __restrict__ Bl, ll ldb,
         bf16* __restrict__ Ch, bf16* __restrict__ Cl, float* __restrict__ Cf, ll ldc,
         int P, ll pA, ll qA, ll pB, ll qB, ll pC, ll qC,
         const float* __restrict__ bias, ll pBias,
         const float* __restrict__ rowadd, ll pRow, ll qRow){
    extern __shared__ char smem[];
    const u32 sb = smem_u32(smem);

    const int tid = threadIdx.x;
    const int lane = tid & 31, wid = tid >> 5;
    const int wm = wid & 1, wn = wid >> 1;

    int z = blockIdx.z, zp = z / P, zq = z - zp*P;
    int col0 = blockIdx.x * 128;
    const bf16* A0h = Ah + (size_t)(zp*pA + zq*qA);
    const bf16* A0l = Al + (size_t)(zp*pA + zq*qA);
    const bf16* B0h = Bh + (size_t)(zp*pB + zq*qB) + (size_t)col0*ldb;
    const bf16* B0l = Bl + (size_t)(zp*pB + zq*qB) + (size_t)col0*ldb;

    const int cr0 = tid >> 2;
    const int cs  = tid & 3;
    auto issue = [&](int c){
        int k0 = c * 32;
        const bf16* s0 = A0h + k0; const bf16* s1 = A0l + k0;
        const bf16* s2 = B0h + k0; const bf16* s3 = B0l + k0;
        u32 base = sb + (u32)(c & 1) * STAGE_B;
        #pragma unroll
        for (int rep = 0; rep < 2; rep++){
            int row = cr0 + rep*64;
            u32 doff = (u32)(row*80 + cs*16);
            cpasync16(base + 0*TILE_B + doff, s0 + (size_t)row*lda + cs*8);
            cpasync16(base + 1*TILE_B + doff, s1 + (size_t)row*lda + cs*8);
            cpasync16(base + 2*TILE_B + doff, s2 + (size_t)row*ldb + cs*8);
            cpasync16(base + 3*TILE_B + doff, s3 + (size_t)row*ldb + cs*8);
        }
        CP_COMMIT();
    };

    float acc[4][4][4];
    #pragma unroll
    for (int i = 0; i < 4; i++)
        #pragma unroll
        for (int j = 0; j < 4; j++)
            #pragma unroll
            for (int k = 0; k < 4; k++) acc[i][j][k] = 0.f;

    const int arow = wm*64 + (lane & 15);
    const int aseg = (lane >> 4) * 8;
    const int bg   = lane >> 3;
    const int brow_in = (lane & 7);
    const int brow_base = wn*32 + ((bg >> 1) << 3) + brow_in;
    const int bseg = (bg & 1) * 8;

    issue(0);

    #pragma unroll 1
    for (int c = 0; c < KCH; ++c){
        CP_WAIT0();
        __syncthreads();
        if (c + 1 < KCH) issue(c + 1);

        u32 sbase = sb + (u32)(c & 1) * STAGE_B;
        #pragma unroll
        for (int ks = 0; ks < 2; ks++){
            u32 ah[4][4], al[4][4];
            u32 bh[2][4], blf[2][4];
            #pragma unroll
            for (int mi = 0; mi < 4; mi++)
                ldsm4(ah[mi], sbase + (u32)((arow + mi*16)*40 + ks*16 + aseg)*2u);
            #pragma unroll
            for (int nh = 0; nh < 2; nh++)
                ldsm4(bh[nh], sbase + 2u*TILE_B + (u32)((brow_base + nh*16)*40 + ks*16 + bseg)*2u);
            #pragma unroll
            for (int nh = 0; nh < 2; nh++)
                ldsm4(blf[nh], sbase + 3u*TILE_B + (u32)((brow_base + nh*16)*40 + ks*16 + bseg)*2u);
            #pragma unroll
            for (int mi = 0; mi < 4; mi++)
                ldsm4(al[mi], sbase + TILE_B + (u32)((arow + mi*16)*40 + ks*16 + aseg)*2u);

            #pragma unroll
            for (int mi = 0; mi < 4; mi++)
                #pragma unroll
                for (int ni = 0; ni < 4; ni++)
                    mma16816(acc[mi][ni], ah[mi], bh[ni>>1][(ni&1)*2], bh[ni>>1][(ni&1)*2+1]);
            #pragma unroll
            for (int mi = 0; mi < 4; mi++)
                #pragma unroll
                for (int ni = 0; ni < 4; ni++)
                    mma16816(acc[mi][ni], ah[mi], blf[ni>>1][(ni&1)*2], blf[ni>>1][(ni&1)*2+1]);
            #pragma unroll
            for (int mi = 0; mi < 4; mi++)
                #pragma unroll
                for (int ni = 0; ni < 4; ni++)
                    mma16816(acc[mi][ni], al[mi], bh[ni>>1][(ni&1)*2], bh[ni>>1][(ni&1)*2+1]);
        }
    }

    ll cofs = (ll)zp*pC + (ll)zq*qC;
    const float* bp = (EPI == 0) ? (bias + zp*pBias) : nullptr;
    const float* rp = (EPI == 1) ? (rowadd + zp*pRow + zq*qRow) : nullptr;

    #pragma unroll
    for (int mi = 0; mi < 4; mi++){
        int rr = wm*64 + mi*16 + (lane >> 2);
        #pragma unroll
        for (int ni = 0; ni < 4; ni++){
            int cc = col0 + wn*32 + ni*8 + (lane & 3)*2;
            float* cr = acc[mi][ni];
            if (EPI == 0){
                float bv0 = bp[cc], bv1 = bp[cc+1];
                u32 h0, l0, h1, l1;
                split2(cr[0]+bv0, cr[1]+bv1, h0, l0);
                split2(cr[2]+bv0, cr[3]+bv1, h1, l1);
                *(u32*)(Ch + cofs + (size_t)rr*ldc + cc)     = h0;
                *(u32*)(Cl + cofs + (size_t)rr*ldc + cc)     = l0;
                *(u32*)(Ch + cofs + (size_t)(rr+8)*ldc + cc) = h1;
                *(u32*)(Cl + cofs + (size_t)(rr+8)*ldc + cc) = l1;
            } else if (EPI == 1){
                float r0 = rp[rr], r1 = rp[rr+8];
                *(float2*)(Cf + cofs + (size_t)rr*ldc + cc)     = make_float2(cr[0]+r0, cr[1]+r0);
                *(float2*)(Cf + cofs + (size_t)(rr+8)*ldc + cc) = make_float2(cr[2]+r1, cr[3]+r1);
            } else {
                float* p0 = Cf + cofs + (size_t)rr*ldc + cc;
                float* p1 = Cf + cofs + (size_t)(rr+8)*ldc + cc;
                p0[0] = cr[0]; p0[1] = cr[1];
                p1[0] = cr[2]; p1[1] = cr[3];
            }
        }
    }
}

// ---------------- bias rows (exact fp32) ----------------
__global__ void bias_kernel(const float* __restrict__ yrf,
                            const float* __restrict__ brel, const float* __restrict__ barc,
                            float* __restrict__ rrel, float* __restrict__ rarc){
    int y = blockIdx.x, b = blockIdx.y, t = threadIdx.x;
    __shared__ float sy[PK];
    const float* yrow = yrf + ((size_t)b*Yn + y)*PK;
    for (int h = t; h < PK; h += 256) sy[h] = yrow[h];
    __syncthreads();
    int w = t >> 5, lane = t & 31;
    for (int o = w; o < Ln; o += 8){
        const float* wr = brel + (size_t)o*H1n;
        float s = 0.f;
        for (int j = lane; j < Hn; j += 32) s += wr[j]*sy[j];
        #pragma unroll
        for (int off = 16; off; off >>= 1) s += __shfl_xor_sync(0xffffffffu, s, off);
        if (lane == 0) rrel[((size_t)b*Yn + y)*Ln + o] = s + wr[Hn];
    }
    if (w == 0){
        float s = 0.f;
        for (int j = lane; j < Hn; j += 32) s += barc[j]*sy[j];
        #pragma unroll
        for (int off = 16; off; off >>= 1) s += __shfl_xor_sync(0xffffffffu, s, off);
        if (lane == 0) rarc[(size_t)b*Yn + y] = s;
    }
}

// ---------------- transpose / fill / loss ----------------
__global__ void transpose_rel(const float* __restrict__ R, float* __restrict__ out){
    __shared__ float sm[Ln][129];
    int x = blockIdx.x, b = blockIdx.y, y0 = blockIdx.z * 128;
    int t = threadIdx.x;
    for (int i = t; i < Ln*128; i += 256){
        int o = i >> 7, y = i & 127;
        sm[o][y] = R[(((size_t)b*Ln + o)*128 + x)*Yn + y0 + y];
    }
    __syncthreads();
    float* dst = out + ((size_t)(b*Sn + x)*Yn + y0)*Ln;
    for (int i = t; i < 128*Ln; i += 256) dst[i] = sm[i % Ln][i / Ln];
}

__global__ void fill_kernel(const float* __restrict__ rrel, const float* __restrict__ rarc,
                            float* __restrict__ out_rel, float* __restrict__ out_arc){
    int x = 128 + blockIdx.x, b = blockIdx.y, t = threadIdx.x;
    const int YL = Yn*Ln;
    float* dr = out_rel + ((size_t)(b*Sn + x))*YL;
    const float* sr = rrel + (size_t)b*YL;
    for (int i = t; i < YL; i += 256) dr[i] = sr[i];
    float* da = out_arc + ((size_t)(b*Sn + x))*Yn;
    const float* sa = rarc + (size_t)b*Yn;
    for (int i = t; i < Yn; i += 256) da[i] = sa[i];
}

__global__ void loss_kernel(const float* __restrict__ rel, const float* __restrict__ arc,
                            const int* __restrict__ la, const int* __restrict__ lr){
    int x = blockIdx.x, b = blockIdx.y, t = threadIdx.x;
    int lab = la[b*Sn + x];
    if (lab == 0) return;
    int ys = lab; if (ys < 0) ys = 0; if (ys > Yn-1) ys = Yn-1;
    const float* row = arc + ((size_t)(b*Sn + x))*Yn;
    __shared__ float red[256];
    float v = fmaxf(row[t], row[t+256]);
    red[t] = v; __syncthreads();
    for (int s2 = 128; s2 > 0; s2 >>= 1){ if (t < s2) red[t] = fmaxf(red[t], red[t+s2]); __syncthreads(); }
    float mx = red[0]; __syncthreads();
    float e = __expf(row[t]-mx) + __expf(row[t+256]-mx);
    red[t] = e; __syncthreads();
    for (int s2 = 128; s2 > 0; s2 >>= 1){ if (t < s2) red[t] += red[t+s2]; __syncthreads(); }
    float lse = mx + logf(red[0]);
    if (t == 0) atomicAdd(&g_arc_sum, lse - row[ys]);
    __shared__ float rv[Ln];
    const float* rrow = rel + (((size_t)(b*Sn + x))*Yn + ys)*Ln;
    if (t < Ln) rv[t] = rrow[t];
    __syncthreads();
    if (t == 0){
        float m2 = rv[0];
        #pragma unroll
        for (int o = 1; o < Ln; o++) m2 = fmaxf(m2, rv[o]);
        float s = 0.f;
        #pragma unroll
        for (int o = 0; o < Ln; o++) s += __expf(rv[o]-m2);
        int rl = lr[b*Sn + x];
        atomicAdd(&g_rel_sum, -(rv[rl] - m2 - logf(s)));
    }
}

__global__ void finalize_kernel(float* __restrict__ out){
    out[0] = (g_arc_sum + g_rel_sum) / (float)g_n;
}

// ---------------- launch ----------------
extern "C" void kernel_launch(void* const* d_in, const int* in_sizes, int n_in,
                              void* d_out_v, int out_size){
    const float* hidden      = (const float*)d_in[0];
    const float* W_arc       = (const float*)d_in[1];
    const float* W_rel       = (const float*)d_in[2];
    const int*   word_starts = (const int*)d_in[3];
    const int*   labels_arcs = (const int*)d_in[4];
    const int*   labels_rels = (const int*)d_in[5];

    float* out     = (float*)d_out_v;
    float* out_rel = out + 1;
    float* out_arc = out + 1 + (size_t)Bn*Sn*Yn*Ln;

    bf16 *xah,*xal,*yrh,*yrl,*Wrh,*Wrl,*Wah,*Wal,*Th,*Tl,*Uh,*Ul;
    float *xaf,*yrf,*brel,*wcol,*barc,*tcol,*R,*rrel,*rarc;
    cudaGetSymbolAddress((void**)&xah, g_xa_h);  cudaGetSymbolAddress((void**)&xal, g_xa_l);
    cudaGetSymbolAddress((void**)&xaf, g_xaf);
    cudaGetSymbolAddress((void**)&yrh, g_yr_h);  cudaGetSymbolAddress((void**)&yrl, g_yr_l);
    cudaGetSymbolAddress((void**)&yrf, g_yrf);
    cudaGetSymbolAddress((void**)&Wrh, g_Wrt_h); cudaGetSymbolAddress((void**)&Wrl, g_Wrt_l);
    cudaGetSymbolAddress((void**)&Wah, g_Wat_h); cudaGetSymbolAddress((void**)&Wal, g_Wat_l);
    cudaGetSymbolAddress((void**)&brel, g_brel); cudaGetSymbolAddress((void**)&wcol, g_wcol);
    cudaGetSymbolAddress((void**)&barc, g_barc); cudaGetSymbolAddress((void**)&tcol, g_tcol);
    cudaGetSymbolAddress((void**)&Th,  g_T_h);   cudaGetSymbolAddress((void**)&Tl,  g_T_l);
    cudaGetSymbolAddress((void**)&Uh,  g_U_h);   cudaGetSymbolAddress((void**)&Ul,  g_U_l);
    cudaGetSymbolAddress((void**)&R,   g_R);
    cudaGetSymbolAddress((void**)&rrel, g_rrel); cudaGetSymbolAddress((void**)&rarc, g_rarc);

    cudaFuncSetAttribute(mma_gemm<0>, cudaFuncAttributeMaxDynamicSharedMemorySize, SMEM_DYN);
    cudaFuncSetAttribute(mma_gemm<1>, cudaFuncAttributeMaxDynamicSharedMemorySize, SMEM_DYN);
    cudaFuncSetAttribute(mma_gemm<2>, cudaFuncAttributeMaxDynamicSharedMemorySize, SMEM_DYN);

    static cudaStream_t s2 = nullptr;
    static cudaEvent_t evFork = nullptr, evBuild = nullptr, evTcol = nullptr, evS2 = nullptr;
    if (!s2){
        cudaStreamCreateWithFlags(&s2, cudaStreamNonBlocking);
        cudaEventCreateWithFlags(&evFork,  cudaEventDisableTiming);
        cudaEventCreateWithFlags(&evBuild, cudaEventDisableTiming);
        cudaEventCreateWithFlags(&evTcol,  cudaEventDisableTiming);
        cudaEventCreateWithFlags(&evS2,    cudaEventDisableTiming);
    }

    // ---- main stream head: first captured node, then fork ----
    extract_bias<<<Ln + 1, 256>>>(W_rel, W_arc, brel, wcol, barc);
    cudaEventRecord(evFork, 0);

    // ---- side stream (joined to capture via evFork): build/prep/tcol + arc + bias/fill ----
    cudaStreamWaitEvent(s2, evFork, 0);
    build_kernel<<<dim3(Sn, Bn), 256, 0, s2>>>(hidden, word_starts, xah, xal, xaf, yrh, yrl, yrf);
    prep_kernel<<<1, 256, 0, s2>>>(labels_arcs);
    cudaEventRecord(evBuild, s2);
    tcol_kernel<<<dim3(Ln, Bn), 256, 0, s2>>>(xaf, wcol, tcol);
    cudaEventRecord(evTcol, s2);
    repack_warc<<<dim3(24, 24), 256, 0, s2>>>(W_arc, Wah, Wal);
    mma_gemm<0><<<dim3(6, 1, Bn), 256, SMEM_DYN, s2>>>(
        xah, xal, PK, Wah, Wal, PK, Uh, Ul, nullptr, PK,
        1,
        (ll)128*PK, 0LL,
        0LL, 0LL,
        (ll)128*PK, 0LL,
        barc, 0LL,
        nullptr, 0LL, 0LL);
    mma_gemm<2><<<dim3(4, 1, Bn), 256, SMEM_DYN, s2>>>(
        Uh, Ul, PK, yrh, yrl, PK, nullptr, nullptr, out_arc, Yn,
        1,
        (ll)128*PK, 0LL,
        (ll)Yn*PK, 0LL,
        (ll)Sn*Yn, 0LL,
        nullptr, 0LL,
        nullptr, 0LL, 0LL);
    bias_kernel<<<dim3(Yn, Bn), 256, 0, s2>>>(yrf, brel, barc, rrel, rarc);
    fill_kernel<<<dim3(128, Bn), 256, 0, s2>>>(rrel, rarc, out_rel, out_arc);
    cudaEventRecord(evS2, s2);

    // ---- main stream: repack_wrel runs parallel to side-stream work ----
    repack_wrel<<<dim3(24, 24, Ln), 256>>>(W_rel, Wrh, Wrl);

    // rel1 needs xa (build) -> wait evBuild
    cudaStreamWaitEvent(0, evBuild, 0);
    mma_gemm<0><<<dim3(6, 1, Ln*Bn), 256, SMEM_DYN>>>(
        xah, xal, PK, Wrh, Wrl, PK, Th, Tl, nullptr, PK,
        Bn,
        0LL, (ll)128*PK,
        (ll)PK*PK, 0LL,
        (ll)128*PK, (ll)Ln*128*PK,
        brel, (ll)H1n,
        nullptr, 0LL, 0LL);

    // rel2 needs tcol -> wait evTcol
    cudaStreamWaitEvent(0, evTcol, 0);
    mma_gemm<1><<<dim3(4, 1, Bn*Ln), 256, SMEM_DYN>>>(
        Th, Tl, PK, yrh, yrl, PK, nullptr, nullptr, R, Yn,
        Ln,
        (ll)Ln*128*PK, (ll)128*PK,
        (ll)Yn*PK, 0LL,
        (ll)Ln*128*Yn, (ll)128*Yn,
        nullptr, 0LL,
        tcol, (ll)Ln*128, 128LL);

    transpose_rel<<<dim3(128, Bn, 4), 256>>>(R, out_rel);

    // ---- join, then loss ----
    cudaStreamWaitEvent(0, evS2, 0);
    loss_kernel<<<dim3(Sn, Bn), 256>>>(out_rel, out_arc, labels_arcs, labels_rels);
    finalize_kernel<<<1, 1>>>(out);
}

// round 14
// speedup vs baseline: 1.4202x; 1.3479x over previous
#include <cuda_runtime.h>
#include <cuda_fp16.h>
#include <cstdint>
#include <math.h>

#define Bn  16
#define Sn  256
#define Hn  768
#define H1n 769
#define Ln  37
#define Yn  512
#define PK  768
#define KCH 24

typedef long long ll;
typedef unsigned int u32;
typedef __half f16;

#define TILE_B   10240     // 128 rows x 40 f16 (80B padded rows)
#define STAGE_B  30720     // 3 tiles per stage (Ah, Bh, Bl)
#define SMEM_DYN 61440

// ---------------- static scratch ----------------
__device__ __align__(256) f16   g_xa_h[(size_t)Bn*128*PK];
__device__ __align__(256) float g_xaf [(size_t)Bn*128*PK];
__device__ __align__(256) f16   g_yr_h[(size_t)Bn*Yn*PK];
__device__ __align__(256) f16   g_yr_l[(size_t)Bn*Yn*PK];
__device__ __align__(256) float g_yrf [(size_t)Bn*Yn*PK];
__device__ __align__(256) f16   g_Wrt_h[(size_t)Ln*PK*PK];
__device__ __align__(256) f16   g_Wrt_l[(size_t)Ln*PK*PK];
__device__ __align__(256) f16   g_Wat_h[(size_t)PK*PK];
__device__ __align__(256) f16   g_Wat_l[(size_t)PK*PK];
__device__ __align__(256) float g_brel[(size_t)Ln*H1n];
__device__ __align__(256) float g_wcol[(size_t)Ln*H1n];
__device__ __align__(256) float g_barc[(size_t)Hn];
__device__ __align__(256) f16   g_T_h[(size_t)Bn*Ln*128*PK];
__device__ __align__(256) f16   g_U_h[(size_t)Bn*128*PK];
__device__ __align__(256) float g_tcol[(size_t)Bn*Ln*128];
__device__ __align__(256) float g_R[(size_t)Bn*Ln*128*Yn];
__device__ float g_rrel[(size_t)Bn*Yn*Ln];
__device__ float g_rarc[(size_t)Bn*Yn];
__device__ float g_arc_sum, g_rel_sum;
__device__ int   g_n;

// ---------------- helpers ----------------
__device__ __forceinline__ u32 smem_u32(const void* p){
    u32 a; asm("{ .reg .u64 t; cvta.to.shared.u64 t, %1; cvt.u32.u64 %0, t; }" : "=r"(a) : "l"(p));
    return a;
}
__device__ __forceinline__ void ldsm4(u32* d, u32 addr){
    asm volatile("ldmatrix.sync.aligned.m8n8.x4.shared.b16 {%0,%1,%2,%3}, [%4];"
        : "=r"(d[0]), "=r"(d[1]), "=r"(d[2]), "=r"(d[3]) : "r"(addr));
}
__device__ __forceinline__ void mma16816(float* c, const u32* a, u32 b0, u32 b1){
    asm volatile("mma.sync.aligned.m16n8k16.row.col.f32.f16.f16.f32 "
        "{%0,%1,%2,%3}, {%4,%5,%6,%7}, {%8,%9}, {%0,%1,%2,%3};"
        : "+f"(c[0]), "+f"(c[1]), "+f"(c[2]), "+f"(c[3])
        : "r"(a[0]), "r"(a[1]), "r"(a[2]), "r"(a[3]), "r"(b0), "r"(b1));
}
__device__ __forceinline__ void cpasync16(u32 dst, const void* src){
    asm volatile("cp.async.cg.shared.global [%0], [%1], 16;" :: "r"(dst), "l"(src) : "memory");
}
#define CP_COMMIT() asm volatile("cp.async.commit_group;" ::: "memory")
#define CP_WAIT0()  asm volatile("cp.async.wait_group 0;" ::: "memory")

// pack two floats to f16x2 (RN)
__device__ __forceinline__ u32 packh2(float f0, float f1){
    u32 h;
    asm("cvt.rn.f16x2.f32 %0, %1, %2;" : "=r"(h) : "f"(f1), "f"(f0));
    return h;
}
__device__ __forceinline__ void splith(float v, f16& h, f16& l){
    h = __float2half_rn(v);
    l = __float2half_rn(v - __half2float(h));
}

// ---------------- weight repack: transpose + fp16 split ----------------
__global__ void repack_wrel(const float* __restrict__ W, f16* __restrict__ Wh, f16* __restrict__ Wl){
    __shared__ float sm[32][33];
    int o = blockIdx.z, i0 = blockIdx.x*32, j0 = blockIdx.y*32;
    int tx = threadIdx.x & 31, ty = threadIdx.x >> 5;
    for (int r = ty; r < 32; r += 8)
        sm[r][tx] = W[((size_t)o*H1n + i0 + r)*H1n + j0 + tx];
    __syncthreads();
    for (int r = ty; r < 32; r += 8){
        int j = j0 + r, i = i0 + tx;
        float v = sm[tx][r];
        f16 h, l; splith(v, h, l);
        size_t d = ((size_t)o*PK + j)*PK + i;
        Wh[d] = h; Wl[d] = l;
    }
}
__global__ void repack_warc(const float* __restrict__ W, f16* __restrict__ Wh, f16* __restrict__ Wl){
    __shared__ float sm[32][33];
    int i0 = blockIdx.x*32, j0 = blockIdx.y*32;
    int tx = threadIdx.x & 31, ty = threadIdx.x >> 5;
    for (int r = ty; r < 32; r += 8)
        sm[r][tx] = W[(size_t)(i0 + r)*Hn + j0 + tx];
    __syncthreads();
    for (int r = ty; r < 32; r += 8){
        int j = j0 + r, i = i0 + tx;
        float v = sm[tx][r];
        f16 h, l; splith(v, h, l);
        size_t d = (size_t)j*PK + i;
        Wh[d] = h; Wl[d] = l;
    }
}

__global__ void extract_bias(const float* __restrict__ Wrel, const float* __restrict__ Warc,
                             float* __restrict__ brel, float* __restrict__ wcol, float* __restrict__ barc){
    int o = blockIdx.x, t = threadIdx.x;
    if (o < Ln){
        for (int j = t; j < H1n; j += 256){
            brel[(size_t)o*H1n + j] = Wrel[((size_t)o*H1n + Hn)*H1n + j];
            wcol[(size_t)o*H1n + j] = Wrel[((size_t)o*H1n + j)*H1n + Hn];
        }
    } else {
        for (int j = t; j < Hn; j += 256) barc[j] = Warc[(size_t)Hn*Hn + j];
    }
}

// ---------------- build xa/yr (segment mean, fp16 split) ----------------
__global__ void build_kernel(const float* __restrict__ hidden, const int* __restrict__ ws,
                             f16* __restrict__ xah, float* __restrict__ xaf,
                             f16* __restrict__ yrh, f16* __restrict__ yrl, float* __restrict__ yrf){
    int j = blockIdx.x, b = blockIdx.y, t = threadIdx.x;
    __shared__ int sws[Sn];
    int myws = ws[b*Sn + t];
    sws[t] = myws;
    int n_valid = __syncthreads_count(myws != 0);
    int start = sws[j];
    int end = (j+1 < Sn) ? sws[j+1] : 0;
    bool valid = (j+1) < n_valid;
    int len = end - start; if (len < 1) len = 1;
    float inv = 1.0f/(float)len;
    const float* hb = hidden + (size_t)b*Sn*Hn;
    size_t yj = ((size_t)b*Yn + j)*PK;
    size_t yd = ((size_t)b*Yn + Sn + j)*PK;
    size_t xj = ((size_t)b*128 + j)*PK;
    for (int h = t; h < PK; h += 256){
        float hv = hb[(size_t)j*Hn + h];
        float dv = 0.f;
        if (valid){
            float s = 0.f;
            for (int tok = start; tok < end; ++tok) s += hb[(size_t)tok*Hn + h];
            dv = s*inv;
        }
        f16 hh, hl, dh, dl;
        splith(hv, hh, hl);
        splith(dv, dh, dl);
        yrh[yj+h] = hh; yrl[yj+h] = hl; yrf[yj+h] = hv;
        yrh[yd+h] = dh; yrl[yd+h] = dl; yrf[yd+h] = dv;
        if (j < 128){ xah[xj+h] = dh; xaf[xj+h] = dv; }
    }
}

__global__ void prep_kernel(const int* __restrict__ la){
    int t = threadIdx.x, cnt = 0;
    for (int i = t; i < Bn*Sn; i += 256) cnt += (la[i] != 0);
    __shared__ int sc[256];
    sc[t] = cnt; __syncthreads();
    for (int s2 = 128; s2 > 0; s2 >>= 1){ if (t < s2) sc[t] += sc[t+s2]; __syncthreads(); }
    if (t == 0){ g_n = sc[0]; g_arc_sum = 0.f; g_rel_sum = 0.f; }
}

// tcol[b][o][x] = dot(xaf[b][x], wcol[o][:768]) + wcol[o][768]  (exact fp32)
__global__ void tcol_kernel(const float* __restrict__ xaf, const float* __restrict__ wcol,
                            float* __restrict__ tcol){
    int o = blockIdx.x, b = blockIdx.y;
    int t = threadIdx.x, w = t >> 5, lane = t & 31;
    __shared__ float sw[PK];
    for (int i = t; i < PK; i += 256) sw[i] = wcol[(size_t)o*H1n + i];
    __syncthreads();
    float cbias = wcol[(size_t)o*H1n + Hn];
    for (int x = w; x < 128; x += 8){
        const float* xr = xaf + ((size_t)b*128 + x)*PK;
        float s = 0.f;
        #pragma unroll 4
        for (int i = lane; i < PK; i += 32) s += xr[i]*sw[i];
        #pragma unroll
        for (int off = 16; off; off >>= 1) s += __shfl_xor_sync(0xffffffffu, s, off);
        if (lane == 0) tcol[((size_t)b*Ln + o)*128 + x] = s + cbias;
    }
}

// ---------------- HMMA GEMM, fp16 2-pass (hh + hl), cp.async 2-stage, 2 CTAs/SM ----------------
// A: [128,PK] hi only (lda). B: [N,PK] hi/lo K-major (ldb).
// EPI 0: +bias row (fp32), round -> Ch fp16.   EPI 1: +rowadd[rr], fp32 float2.
// EPI 2: fp32 scalar stores (4B-aligned dest).
template<int EPI>
__global__ void __launch_bounds__(256, 2)
mma_gemm(const f16* __restrict__ Ah, ll lda,
         const f16* __restrict__ Bh, const f16* __restrict__ Bl, ll ldb,
         f16* __restrict__ Ch, float* __restrict__ Cf, ll ldc,
         int P, ll pA, ll qA, ll pB, ll qB, ll pC, ll qC,
         const float* __restrict__ bias, ll pBias,
         const float* __restrict__ rowadd, ll pRow, ll qRow){
    extern __shared__ char smem[];
    const u32 sb = smem_u32(smem);

    const int tid = threadIdx.x;
    const int lane = tid & 31, wid = tid >> 5;
    const int wm = wid & 1, wn = wid >> 1;

    int z = blockIdx.z, zp = z / P, zq = z - zp*P;
    int col0 = blockIdx.x * 128;
    const f16* A0h = Ah + (size_t)(zp*pA + zq*qA);
    const f16* B0h = Bh + (size_t)(zp*pB + zq*qB) + (size_t)col0*ldb;
    const f16* B0l = Bl + (size_t)(zp*pB + zq*qB) + (size_t)col0*ldb;

    const int cr0 = tid >> 2;
    const int cs  = tid & 3;
    auto issue = [&](int c){
        int k0 = c * 32;
        const f16* s0 = A0h + k0;
        const f16* s1 = B0h + k0;
        const f16* s2 = B0l + k0;
        u32 base = sb + (u32)(c & 1) * STAGE_B;
        #pragma unroll
        for (int rep = 0; rep < 2; rep++){
            int row = cr0 + rep*64;
            u32 doff = (u32)(row*80 + cs*16);
            cpasync16(base + 0*TILE_B + doff, s0 + (size_t)row*lda + cs*8);
            cpasync16(base + 1*TILE_B + doff, s1 + (size_t)row*ldb + cs*8);
            cpasync16(base + 2*TILE_B + doff, s2 + (size_t)row*ldb + cs*8);
        }
        CP_COMMIT();
    };

    float acc[4][4][4];
    #pragma unroll
    for (int i = 0; i < 4; i++)
        #pragma unroll
        for (int j = 0; j < 4; j++)
            #pragma unroll
            for (int k = 0; k < 4; k++) acc[i][j][k] = 0.f;

    const int arow = wm*64 + (lane & 15);
    const int aseg = (lane >> 4) * 8;
    const int bg   = lane >> 3;
    const int brow_in = (lane & 7);
    const int brow_base = wn*32 + ((bg >> 1) << 3) + brow_in;
    const int bseg = (bg & 1) * 8;

    issue(0);

    #pragma unroll 1
    for (int c = 0; c < KCH; ++c){
        CP_WAIT0();
        __syncthreads();
        if (c + 1 < KCH) issue(c + 1);

        u32 sbase = sb + (u32)(c & 1) * STAGE_B;
        #pragma unroll
        for (int ks = 0; ks < 2; ks++){
            u32 ah[4][4];
            u32 bh[2][4], blf[2][4];
            #pragma unroll
            for (int mi = 0; mi < 4; mi++)
                ldsm4(ah[mi], sbase + (u32)((arow + mi*16)*40 + ks*16 + aseg)*2u);
            #pragma unroll
            for (int nh = 0; nh < 2; nh++)
                ldsm4(bh[nh], sbase + 1u*TILE_B + (u32)((brow_base + nh*16)*40 + ks*16 + bseg)*2u);
            #pragma unroll
            for (int nh = 0; nh < 2; nh++)
                ldsm4(blf[nh], sbase + 2u*TILE_B + (u32)((brow_base + nh*16)*40 + ks*16 + bseg)*2u);

            // pass hh: Ah x Bh
            #pragma unroll
            for (int mi = 0; mi < 4; mi++)
                #pragma unroll
                for (int ni = 0; ni < 4; ni++)
                    mma16816(acc[mi][ni], ah[mi], bh[ni>>1][(ni&1)*2], bh[ni>>1][(ni&1)*2+1]);
            // pass hl: Ah x Bl
            #pragma unroll
            for (int mi = 0; mi < 4; mi++)
                #pragma unroll
                for (int ni = 0; ni < 4; ni++)
                    mma16816(acc[mi][ni], ah[mi], blf[ni>>1][(ni&1)*2], blf[ni>>1][(ni&1)*2+1]);
        }
    }

    ll cofs = (ll)zp*pC + (ll)zq*qC;
    const float* bp = (EPI == 0) ? (bias + zp*pBias) : nullptr;
    const float* rp = (EPI == 1) ? (rowadd + zp*pRow + zq*qRow) : nullptr;

    #pragma unroll
    for (int mi = 0; mi < 4; mi++){
        int rr = wm*64 + mi*16 + (lane >> 2);
        #pragma unroll
        for (int ni = 0; ni < 4; ni++){
            int cc = col0 + wn*32 + ni*8 + (lane & 3)*2;
            float* cr = acc[mi][ni];
            if (EPI == 0){
                float bv0 = bp[cc], bv1 = bp[cc+1];
                *(u32*)(Ch + cofs + (size_t)rr*ldc + cc)     = packh2(cr[0]+bv0, cr[1]+bv1);
                *(u32*)(Ch + cofs + (size_t)(rr+8)*ldc + cc) = packh2(cr[2]+bv0, cr[3]+bv1);
            } else if (EPI == 1){
                float r0 = rp[rr], r1 = rp[rr+8];
                *(float2*)(Cf + cofs + (size_t)rr*ldc + cc)     = make_float2(cr[0]+r0, cr[1]+r0);
                *(float2*)(Cf + cofs + (size_t)(rr+8)*ldc + cc) = make_float2(cr[2]+r1, cr[3]+r1);
            } else {
                float* p0 = Cf + cofs + (size_t)rr*ldc + cc;
                float* p1 = Cf + cofs + (size_t)(rr+8)*ldc + cc;
                p0[0] = cr[0]; p0[1] = cr[1];
                p1[0] = cr[2]; p1[1] = cr[3];
            }
        }
    }
}

// ---------------- bias rows (exact fp32) ----------------
__global__ void bias_kernel(const float* __restrict__ yrf,
                            const float* __restrict__ brel, const float* __restrict__ barc,
                            float* __restrict__ rrel, float* __restrict__ rarc){
    int y = blockIdx.x, b = blockIdx.y, t = threadIdx.x;
    __shared__ float sy[PK];
    const float* yrow = yrf + ((size_t)b*Yn + y)*PK;
    for (int h = t; h < PK; h += 256) sy[h] = yrow[h];
    __syncthreads();
    int w = t >> 5, lane = t & 31;
    for (int o = w; o < Ln; o += 8){
        const float* wr = brel + (size_t)o*H1n;
        float s = 0.f;
        for (int j = lane; j < Hn; j += 32) s += wr[j]*sy[j];
        #pragma unroll
        for (int off = 16; off; off >>= 1) s += __shfl_xor_sync(0xffffffffu, s, off);
        if (lane == 0) rrel[((size_t)b*Yn + y)*Ln + o] = s + wr[Hn];
    }
    if (w == 0){
        float s = 0.f;
        for (int j = lane; j < Hn; j += 32) s += barc[j]*sy[j];
        #pragma unroll
        for (int off = 16; off; off >>= 1) s += __shfl_xor_sync(0xffffffffu, s, off);
        if (lane == 0) rarc[(size_t)b*Yn + y] = s;
    }
}

// ---------------- transpose / fill / loss ----------------
__global__ void transpose_rel(const float* __restrict__ R, float* __restrict__ out){
    __shared__ float sm[Ln][129];
    int x = blockIdx.x, b = blockIdx.y, y0 = blockIdx.z * 128;
    int t = threadIdx.x;
    for (int i = t; i < Ln*128; i += 256){
        int o = i >> 7, y = i & 127;
        sm[o][y] = R[(((size_t)b*Ln + o)*128 + x)*Yn + y0 + y];
    }
    __syncthreads();
    float* dst = out + ((size_t)(b*Sn + x)*Yn + y0)*Ln;
    for (int i = t; i < 128*Ln; i += 256) dst[i] = sm[i % Ln][i / Ln];
}

__global__ void fill_kernel(const float* __restrict__ rrel, const float* __restrict__ rarc,
                            float* __restrict__ out_rel, float* __restrict__ out_arc){
    int x = 128 + blockIdx.x, b = blockIdx.y, t = threadIdx.x;
    const int YL = Yn*Ln;
    float* dr = out_rel + ((size_t)(b*Sn + x))*YL;
    const float* sr = rrel + (size_t)b*YL;
    for (int i = t; i < YL; i += 256) dr[i] = sr[i];
    float* da = out_arc + ((size_t)(b*Sn + x))*Yn;
    const float* sa = rarc + (size_t)b*Yn;
    for (int i = t; i < Yn; i += 256) da[i] = sa[i];
}

__global__ void loss_kernel(const float* __restrict__ rel, const float* __restrict__ arc,
                            const int* __restrict__ la, const int* __restrict__ lr){
    int x = blockIdx.x, b = blockIdx.y, t = threadIdx.x;
    int lab = la[b*Sn + x];
    if (lab == 0) return;
    int ys = lab; if (ys < 0) ys = 0; if (ys > Yn-1) ys = Yn-1;
    const float* row = arc + ((size_t)(b*Sn + x))*Yn;
    __shared__ float red[256];
    float v = fmaxf(row[t], row[t+256]);
    red[t] = v; __syncthreads();
    for (int s2 = 128; s2 > 0; s2 >>= 1){ if (t < s2) red[t] = fmaxf(red[t], red[t+s2]); __syncthreads(); }
    float mx = red[0]; __syncthreads();
    float e = __expf(row[t]-mx) + __expf(row[t+256]-mx);
    red[t] = e; __syncthreads();
    for (int s2 = 128; s2 > 0; s2 >>= 1){ if (t < s2) red[t] += red[t+s2]; __syncthreads(); }
    float lse = mx + logf(red[0]);
    if (t == 0) atomicAdd(&g_arc_sum, lse - row[ys]);
    __shared__ float rv[Ln];
    const float* rrow = rel + (((size_t)(b*Sn + x))*Yn + ys)*Ln;
    if (t < Ln) rv[t] = rrow[t];
    __syncthreads();
    if (t == 0){
        float m2 = rv[0];
        #pragma unroll
        for (int o = 1; o < Ln; o++) m2 = fmaxf(m2, rv[o]);
        float s = 0.f;
        #pragma unroll
        for (int o = 0; o < Ln; o++) s += __expf(rv[o]-m2);
        int rl = lr[b*Sn + x];
        atomicAdd(&g_rel_sum, -(rv[rl] - m2 - logf(s)));
    }
}

__global__ void finalize_kernel(float* __restrict__ out){
    out[0] = (g_arc_sum + g_rel_sum) / (float)g_n;
}

// ---------------- launch ----------------
extern "C" void kernel_launch(void* const* d_in, const int* in_sizes, int n_in,
                              void* d_out_v, int out_size){
    const float* hidden      = (const float*)d_in[0];
    const float* W_arc       = (const float*)d_in[1];
    const float* W_rel       = (const float*)d_in[2];
    const int*   word_starts = (const int*)d_in[3];
    const int*   labels_arcs = (const int*)d_in[4];
    const int*   labels_rels = (const int*)d_in[5];

    float* out     = (float*)d_out_v;
    float* out_rel = out + 1;
    float* out_arc = out + 1 + (size_t)Bn*Sn*Yn*Ln;

    f16 *xah,*yrh,*yrl,*Wrh,*Wrl,*Wah,*Wal,*Th,*Uh;
    float *xaf,*yrf,*brel,*wcol,*barc,*tcol,*R,*rrel,*rarc;
    cudaGetSymbolAddress((void**)&xah, g_xa_h);
    cudaGetSymbolAddress((void**)&xaf, g_xaf);
    cudaGetSymbolAddress((void**)&yrh, g_yr_h);  cudaGetSymbolAddress((void**)&yrl, g_yr_l);
    cudaGetSymbolAddress((void**)&yrf, g_yrf);
    cudaGetSymbolAddress((void**)&Wrh, g_Wrt_h); cudaGetSymbolAddress((void**)&Wrl, g_Wrt_l);
    cudaGetSymbolAddress((void**)&Wah, g_Wat_h); cudaGetSymbolAddress((void**)&Wal, g_Wat_l);
    cudaGetSymbolAddress((void**)&brel, g_brel); cudaGetSymbolAddress((void**)&wcol, g_wcol);
    cudaGetSymbolAddress((void**)&barc, g_barc); cudaGetSymbolAddress((void**)&tcol, g_tcol);
    cudaGetSymbolAddress((void**)&Th,  g_T_h);
    cudaGetSymbolAddress((void**)&Uh,  g_U_h);
    cudaGetSymbolAddress((void**)&R,   g_R);
    cudaGetSymbolAddress((void**)&rrel, g_rrel); cudaGetSymbolAddress((void**)&rarc, g_rarc);

    cudaFuncSetAttribute(mma_gemm<0>, cudaFuncAttributeMaxDynamicSharedMemorySize, SMEM_DYN);
    cudaFuncSetAttribute(mma_gemm<1>, cudaFuncAttributeMaxDynamicSharedMemorySize, SMEM_DYN);
    cudaFuncSetAttribute(mma_gemm<2>, cudaFuncAttributeMaxDynamicSharedMemorySize, SMEM_DYN);

    static cudaStream_t s2 = nullptr;
    static cudaEvent_t evFork = nullptr, evBuild = nullptr, evTcol = nullptr, evS2 = nullptr;
    if (!s2){
        cudaStreamCreateWithFlags(&s2, cudaStreamNonBlocking);
        cudaEventCreateWithFlags(&evFork,  cudaEventDisableTiming);
        cudaEventCreateWithFlags(&evBuild, cudaEventDisableTiming);
        cudaEventCreateWithFlags(&evTcol,  cudaEventDisableTiming);
        cudaEventCreateWithFlags(&evS2,    cudaEventDisableTiming);
    }

    // ---- main stream head: first captured node, then fork ----
    extract_bias<<<Ln + 1, 256>>>(W_rel, W_arc, brel, wcol, barc);
    cudaEventRecord(evFork, 0);

    // ---- side stream: build/prep/tcol + arc chain + bias/fill ----
    cudaStreamWaitEvent(s2, evFork, 0);
    build_kernel<<<dim3(Sn, Bn), 256, 0, s2>>>(hidden, word_starts, xah, xaf, yrh, yrl, yrf);
    prep_kernel<<<1, 256, 0, s2>>>(labels_arcs);
    cudaEventRecord(evBuild, s2);
    tcol_kernel<<<dim3(Ln, Bn), 256, 0, s2>>>(xaf, wcol, tcol);
    cudaEventRecord(evTcol, s2);
    repack_warc<<<dim3(24, 24), 256, 0, s2>>>(W_arc, Wah, Wal);
    mma_gemm<0><<<dim3(6, 1, Bn), 256, SMEM_DYN, s2>>>(
        xah, PK, Wah, Wal, PK, Uh, nullptr, PK,
        1,
        (ll)128*PK, 0LL,
        0LL, 0LL,
        (ll)128*PK, 0LL,
        barc, 0LL,
        nullptr, 0LL, 0LL);
    mma_gemm<2><<<dim3(4, 1, Bn), 256, SMEM_DYN, s2>>>(
        Uh, PK, yrh, yrl, PK, nullptr, out_arc, Yn,
        1,
        (ll)128*PK, 0LL,
        (ll)Yn*PK, 0LL,
        (ll)Sn*Yn, 0LL,
        nullptr, 0LL,
        nullptr, 0LL, 0LL);
    bias_kernel<<<dim3(Yn, Bn), 256, 0, s2>>>(yrf, brel, barc, rrel, rarc);
    fill_kernel<<<dim3(128, Bn), 256, 0, s2>>>(rrel, rarc, out_rel, out_arc);
    cudaEventRecord(evS2, s2);

    // ---- main stream: repack_wrel parallel to side work ----
    repack_wrel<<<dim3(24, 24, Ln), 256>>>(W_rel, Wrh, Wrl);

    // rel1: T[b,o](128x768) = xa[b] @ Wrt[o]^T + 1(x)brel[o] ; z = o*16 + b
    cudaStreamWaitEvent(0, evBuild, 0);
    mma_gemm<0><<<dim3(6, 1, Ln*Bn), 256, SMEM_DYN>>>(
        xah, PK, Wrh, Wrl, PK, Th, nullptr, PK,
        Bn,
        0LL, (ll)128*PK,
        (ll)PK*PK, 0LL,
        (ll)128*PK, (ll)Ln*128*PK,
        brel, (ll)H1n,
        nullptr, 0LL, 0LL);

    // rel2: R[b,o](128x512) = T[b,o] @ yr[b]^T + tcol[b,o](x)1 ; z = b*37 + o
    cudaStreamWaitEvent(0, evTcol, 0);
    mma_gemm<1><<<dim3(4, 1, Bn*Ln), 256, SMEM_DYN>>>(
        Th, PK, yrh, yrl, PK, nullptr, R, Yn,
        Ln,
        (ll)Ln*128*PK, (ll)128*PK,
        (ll)Yn*PK, 0LL,
        (ll)Ln*128*Yn, (ll)128*Yn,
        nullptr, 0LL,
        tcol, (ll)Ln*128, 128LL);

    transpose_rel<<<dim3(128, Bn, 4), 256>>>(R, out_rel);

    // ---- join, then loss ----
    cudaStreamWaitEvent(0, evS2, 0);
    loss_kernel<<<dim3(Sn, Bn), 256>>>(out_rel, out_arc, labels_arcs, labels_rels);
    finalize_kernel<<<1, 1>>>(out);
}